// round 2
// baseline (speedup 1.0000x reference)
#include <cuda_runtime.h>
#include <math.h>

#define E_DIM 2048
#define B_DIM 2
#define S_DIM 2048
#define R_DIM 128
#define H_DIM 16
#define D_DIM 128
#define T_DIM (S_DIM + R_DIM)   /* 2176 */

// ---------------- scratch (static device allocations; no cudaMalloc) --------
__device__ float g_wq[3][E_DIM * E_DIM];            // dequantized ternary weights
__device__ float g_xq[B_DIM * S_DIM * E_DIM];       // dequantized int8 activations
__device__ float g_qp[B_DIM * S_DIM * E_DIM];       // Q projection
__device__ float g_kp[B_DIM * T_DIM * E_DIM];       // K (quant part + rk)
__device__ float g_vp[B_DIM * T_DIM * E_DIM];       // V (quant part + rv)
__device__ float g_ao[B_DIM * S_DIM * E_DIM];       // attention output
__device__ float g_part[3 * 1024];
__device__ float g_scales[3];

// ---------------- weight scale = mean(|w|) (deterministic 2-pass) ----------
__global__ void absmean_partial(const float* __restrict__ w,
                                float* __restrict__ part, int n) {
    __shared__ float red[256];
    int chunk = n / gridDim.x;
    int base = blockIdx.x * chunk;
    float s = 0.f;
    for (int i = threadIdx.x; i < chunk; i += blockDim.x) s += fabsf(w[base + i]);
    red[threadIdx.x] = s;
    __syncthreads();
    for (int off = 128; off > 0; off >>= 1) {
        if (threadIdx.x < off) red[threadIdx.x] += red[threadIdx.x + off];
        __syncthreads();
    }
    if (threadIdx.x == 0) part[blockIdx.x] = red[0];
}

__global__ void scale_finalize(const float* __restrict__ part,
                               float* __restrict__ scales, int nblk, float inv_n) {
    __shared__ float red[256];
    const float* p = part + blockIdx.x * nblk;
    float s = 0.f;
    for (int i = threadIdx.x; i < nblk; i += blockDim.x) s += p[i];
    red[threadIdx.x] = s;
    __syncthreads();
    for (int off = 128; off > 0; off >>= 1) {
        if (threadIdx.x < off) red[threadIdx.x] += red[threadIdx.x + off];
        __syncthreads();
    }
    if (threadIdx.x == 0) scales[blockIdx.x] = fmaxf(red[0] * inv_n, 1e-5f);
}

// wq = clip(round(w/scale), -1, 1) * scale   (rintf == jnp.round: half-to-even)
__global__ void quant_weight_k(const float* __restrict__ w, float* __restrict__ wq,
                               const float* __restrict__ scales, int sidx, int n) {
    float sc = scales[sidx];
    for (int i = blockIdx.x * blockDim.x + threadIdx.x; i < n;
         i += gridDim.x * blockDim.x) {
        float q = rintf(__fdiv_rn(w[i], sc));
        q = fminf(fmaxf(q, -1.f), 1.f);
        wq[i] = q * sc;
    }
}

// per-token absmax int8 quant: s = 127/clip(max|x|,1e-5); q = clip(round(x*s))/s
__global__ void quant_act_k(const float* __restrict__ x, float* __restrict__ xq) {
    __shared__ float red[256];
    int row = blockIdx.x;
    const float* xr = x + (size_t)row * E_DIM;
    float* qr = xq + (size_t)row * E_DIM;
    float m = 0.f;
    for (int i = threadIdx.x; i < E_DIM; i += blockDim.x) m = fmaxf(m, fabsf(xr[i]));
    red[threadIdx.x] = m;
    __syncthreads();
    for (int off = 128; off > 0; off >>= 1) {
        if (threadIdx.x < off)
            red[threadIdx.x] = fmaxf(red[threadIdx.x], red[threadIdx.x + off]);
        __syncthreads();
    }
    float mx = fmaxf(red[0], 1e-5f);
    float s = __fdiv_rn(127.f, mx);
    for (int i = threadIdx.x; i < E_DIM; i += blockDim.x) {
        float q = rintf(xr[i] * s);
        q = fminf(fmaxf(q, -128.f), 127.f);
        qr[i] = __fdiv_rn(q, s);
    }
}

// ---------------- NT SGEMM: C[M,N] = A[M,K] * W[N,K]^T (+ optional bias) ----
// 128x128x16 tile, 256 threads, 8x8 per thread with "spread" mapping
// (rows ty+16i, cols tx+16j) so all LDS.128 are bank-conflict-free.
struct GemmJobs {
    const float* A[6];
    const float* W[6];
    float* C[6];
    const float* bias;
};

__global__ __launch_bounds__(256) void sgemm_nt(GemmJobs jobs, int M, int N, int K) {
    __shared__ __align__(16) float As[128][20];
    __shared__ __align__(16) float Ws[128][20];
    const float* A = jobs.A[blockIdx.z];
    const float* W = jobs.W[blockIdx.z];
    float* C = jobs.C[blockIdx.z];
    int tid = threadIdx.x;
    int tx = tid & 15, ty = tid >> 4;
    int bm = blockIdx.y * 128, bn = blockIdx.x * 128;

    float acc[8][8];
#pragma unroll
    for (int i = 0; i < 8; i++)
#pragma unroll
        for (int j = 0; j < 8; j++) acc[i][j] = 0.f;

    for (int kt = 0; kt < K; kt += 16) {
#pragma unroll
        for (int it = 0; it < 2; it++) {
            int idx = tid + it * 256;
            int row = idx >> 2, k4 = (idx & 3) * 4;
            *(float4*)&As[row][k4] =
                *(const float4*)&A[(size_t)(bm + row) * K + kt + k4];
            *(float4*)&Ws[row][k4] =
                *(const float4*)&W[(size_t)(bn + row) * K + kt + k4];
        }
        __syncthreads();
#pragma unroll
        for (int k4 = 0; k4 < 16; k4 += 4) {
            float4 a[8], b[8];
#pragma unroll
            for (int i = 0; i < 8; i++) a[i] = *(float4*)&As[ty + 16 * i][k4];
#pragma unroll
            for (int j = 0; j < 8; j++) b[j] = *(float4*)&Ws[tx + 16 * j][k4];
#pragma unroll
            for (int i = 0; i < 8; i++)
#pragma unroll
                for (int j = 0; j < 8; j++)
                    acc[i][j] += a[i].x * b[j].x + a[i].y * b[j].y +
                                 a[i].z * b[j].z + a[i].w * b[j].w;
        }
        __syncthreads();
    }

    const float* bias = jobs.bias;
#pragma unroll
    for (int i = 0; i < 8; i++) {
        int r = bm + ty + 16 * i;
#pragma unroll
        for (int j = 0; j < 8; j++) {
            int c = bn + tx + 16 * j;
            float v = acc[i][j];
            if (bias) v += bias[c];
            C[(size_t)r * N + c] = v;
        }
    }
}

// ---------------- flash attention, fp32, BQ=64, BK=64, D=128 ---------------
// grid (S/64, H, B), 256 threads. Online softmax. Dynamic smem ~85.8 KB.
__global__ __launch_bounds__(256) void attn_k(const float* __restrict__ Q,
                                              const float* __restrict__ Kp,
                                              const float* __restrict__ Vp,
                                              float* __restrict__ O) {
    extern __shared__ float sm[];
    float* Qs  = sm;                  // [64][132]
    float* KVs = sm + 64 * 132;       // [64][132]
    float* Ss  = sm + 2 * 64 * 132;   // [64][68]
    float* mrow = Ss + 64 * 68;       // [64]
    float* lrow = mrow + 64;          // [64]
    float* arow = lrow + 64;          // [64]

    int tid = threadIdx.x;
    int tx = tid & 15, ty = tid >> 4;
    int q0 = blockIdx.x * 64;
    int h = blockIdx.y, b = blockIdx.z;

    const float* Qb = Q + ((size_t)b * S_DIM + q0) * E_DIM + h * D_DIM;
    const float* Kb = Kp + (size_t)b * T_DIM * E_DIM + h * D_DIM;
    const float* Vb = Vp + (size_t)b * T_DIM * E_DIM + h * D_DIM;

#pragma unroll
    for (int it = 0; it < 8; it++) {
        int idx = tid + it * 256;
        int r = idx >> 5, d4 = (idx & 31) * 4;
        *(float4*)&Qs[r * 132 + d4] = *(const float4*)&Qb[(size_t)r * E_DIM + d4];
    }
    if (tid < 64) { mrow[tid] = -1e30f; lrow[tid] = 0.f; }
    float o[4][8];
#pragma unroll
    for (int i = 0; i < 4; i++)
#pragma unroll
        for (int j = 0; j < 8; j++) o[i][j] = 0.f;
    __syncthreads();

    for (int t0 = 0; t0 < T_DIM; t0 += 64) {
        // load K tile
#pragma unroll
        for (int it = 0; it < 8; it++) {
            int idx = tid + it * 256;
            int r = idx >> 5, d4 = (idx & 31) * 4;
            *(float4*)&KVs[r * 132 + d4] =
                *(const float4*)&Kb[(size_t)(t0 + r) * E_DIM + d4];
        }
        __syncthreads();

        // scores: 4x4 per thread, rows ty+16i, cols tx+16j
        float acc[4][4];
#pragma unroll
        for (int i = 0; i < 4; i++)
#pragma unroll
            for (int j = 0; j < 4; j++) acc[i][j] = 0.f;
#pragma unroll 4
        for (int d4 = 0; d4 < 128; d4 += 4) {
            float4 qv[4], kv[4];
#pragma unroll
            for (int i = 0; i < 4; i++)
                qv[i] = *(float4*)&Qs[(ty + 16 * i) * 132 + d4];
#pragma unroll
            for (int j = 0; j < 4; j++)
                kv[j] = *(float4*)&KVs[(tx + 16 * j) * 132 + d4];
#pragma unroll
            for (int i = 0; i < 4; i++)
#pragma unroll
                for (int j = 0; j < 4; j++)
                    acc[i][j] += qv[i].x * kv[j].x + qv[i].y * kv[j].y +
                                 qv[i].z * kv[j].z + qv[i].w * kv[j].w;
        }
        const float scl = 0.08838834764831845f;  // 1/sqrt(128)
#pragma unroll
        for (int i = 0; i < 4; i++)
#pragma unroll
            for (int j = 0; j < 4; j++)
                Ss[(ty + 16 * i) * 68 + tx + 16 * j] = acc[i][j] * scl;
        __syncthreads();

        // online softmax: 4 threads per row
        {
            int r = tid >> 2;
            float* srow = Ss + r * 68 + (tid & 3) * 16;
            float mx = -1e30f;
#pragma unroll
            for (int c = 0; c < 16; c++) mx = fmaxf(mx, srow[c]);
            mx = fmaxf(mx, __shfl_xor_sync(0xffffffffu, mx, 1));
            mx = fmaxf(mx, __shfl_xor_sync(0xffffffffu, mx, 2));
            float mo = mrow[r];
            float mn = fmaxf(mo, mx);
            float al = __expf(mo - mn);
            float sum = 0.f;
#pragma unroll
            for (int c = 0; c < 16; c++) {
                float p = __expf(srow[c] - mn);
                srow[c] = p;
                sum += p;
            }
            sum += __shfl_xor_sync(0xffffffffu, sum, 1);
            sum += __shfl_xor_sync(0xffffffffu, sum, 2);
            if ((tid & 3) == 0) {
                mrow[r] = mn;
                arow[r] = al;
                lrow[r] = lrow[r] * al + sum;
            }
        }
        __syncthreads();

        // rescale o, then load V over K
        float al4[4];
#pragma unroll
        for (int i = 0; i < 4; i++) al4[i] = arow[ty + 16 * i];
#pragma unroll
        for (int i = 0; i < 4; i++)
#pragma unroll
            for (int j = 0; j < 8; j++) o[i][j] *= al4[i];
#pragma unroll
        for (int it = 0; it < 8; it++) {
            int idx = tid + it * 256;
            int r = idx >> 5, d4 = (idx & 31) * 4;
            *(float4*)&KVs[r * 132 + d4] =
                *(const float4*)&Vb[(size_t)(t0 + r) * E_DIM + d4];
        }
        __syncthreads();

        // o += P @ V : rows ty+16i, d-cols tx+16j
#pragma unroll 4
        for (int c = 0; c < 64; c++) {
            float p[4], v[8];
#pragma unroll
            for (int i = 0; i < 4; i++) p[i] = Ss[(ty + 16 * i) * 68 + c];
#pragma unroll
            for (int j = 0; j < 8; j++) v[j] = KVs[c * 132 + tx + 16 * j];
#pragma unroll
            for (int i = 0; i < 4; i++)
#pragma unroll
                for (int j = 0; j < 8; j++) o[i][j] += p[i] * v[j];
        }
        __syncthreads();
    }

    float li[4];
#pragma unroll
    for (int i = 0; i < 4; i++) li[i] = __fdiv_rn(1.f, lrow[ty + 16 * i]);
#pragma unroll
    for (int i = 0; i < 4; i++)
#pragma unroll
        for (int j = 0; j < 8; j++)
            O[((size_t)b * S_DIM + q0 + ty + 16 * i) * E_DIM + h * D_DIM + tx +
              16 * j] = o[i][j] * li[i];
}

// ---------------- launcher --------------------------------------------------
extern "C" void kernel_launch(void* const* d_in, const int* in_sizes, int n_in,
                              void* d_out, int out_size) {
    const float* x  = (const float*)d_in[0];
    const float* rt = (const float*)d_in[1];
    const float* qw = (const float*)d_in[2];
    const float* kw = (const float*)d_in[3];
    const float* vw = (const float*)d_in[4];
    const float* ow = (const float*)d_in[5];
    const float* ob = (const float*)d_in[6];
    float* out = (float*)d_out;

    float *p_wq, *p_xq, *p_q, *p_k, *p_v, *p_ao, *p_part, *p_scales;
    cudaGetSymbolAddress((void**)&p_wq, g_wq);
    cudaGetSymbolAddress((void**)&p_xq, g_xq);
    cudaGetSymbolAddress((void**)&p_q, g_qp);
    cudaGetSymbolAddress((void**)&p_k, g_kp);
    cudaGetSymbolAddress((void**)&p_v, g_vp);
    cudaGetSymbolAddress((void**)&p_ao, g_ao);
    cudaGetSymbolAddress((void**)&p_part, g_part);
    cudaGetSymbolAddress((void**)&p_scales, g_scales);

    const int n = E_DIM * E_DIM;

    // 1. ternary weight scales + quantized weights
    absmean_partial<<<1024, 256>>>(qw, p_part + 0 * 1024, n);
    absmean_partial<<<1024, 256>>>(kw, p_part + 1 * 1024, n);
    absmean_partial<<<1024, 256>>>(vw, p_part + 2 * 1024, n);
    scale_finalize<<<3, 256>>>(p_part, p_scales, 1024, 1.f / (float)n);
    quant_weight_k<<<2048, 256>>>(qw, p_wq + 0 * (size_t)n, p_scales, 0, n);
    quant_weight_k<<<2048, 256>>>(kw, p_wq + 1 * (size_t)n, p_scales, 1, n);
    quant_weight_k<<<2048, 256>>>(vw, p_wq + 2 * (size_t)n, p_scales, 2, n);

    // 2. per-token activation quant
    quant_act_k<<<B_DIM * S_DIM, 256>>>(x, p_xq);

    // 3. QKV projections (quantized): 6 jobs (3 weights x 2 batches), M=2048
    GemmJobs j1 = {};
    for (int z = 0; z < 6; z++) {
        int w = z >> 1, batch = z & 1;
        j1.A[z] = p_xq + (size_t)batch * S_DIM * E_DIM;
        j1.W[z] = p_wq + (size_t)w * n;
        if (w == 0)
            j1.C[z] = p_q + (size_t)batch * S_DIM * E_DIM;
        else if (w == 1)
            j1.C[z] = p_k + (size_t)batch * T_DIM * E_DIM;
        else
            j1.C[z] = p_v + (size_t)batch * T_DIM * E_DIM;
    }
    j1.bias = nullptr;
    sgemm_nt<<<dim3(16, 16, 6), 256>>>(j1, S_DIM, E_DIM, E_DIM);

    // 4. reasoning rk/rv (UNquantized weights), M=128, appended at row S
    GemmJobs j2 = {};
    for (int z = 0; z < 4; z++) {
        int w = z >> 1, batch = z & 1;
        j2.A[z] = rt + (size_t)batch * R_DIM * E_DIM;
        j2.W[z] = (w == 0) ? kw : vw;
        j2.C[z] = ((w == 0) ? p_k : p_v) + (size_t)batch * T_DIM * E_DIM +
                  (size_t)S_DIM * E_DIM;
    }
    j2.bias = nullptr;
    sgemm_nt<<<dim3(16, 1, 4), 256>>>(j2, R_DIM, E_DIM, E_DIM);

    // 5. attention
    const int ATT_SMEM = (2 * 64 * 132 + 64 * 68 + 3 * 64) * 4;  // 85760 B
    cudaFuncSetAttribute(attn_k, cudaFuncAttributeMaxDynamicSharedMemorySize,
                         ATT_SMEM);
    attn_k<<<dim3(S_DIM / 64, H_DIM, B_DIM), 256, ATT_SMEM>>>(p_q, p_k, p_v, p_ao);

    // 6. output projection + bias
    GemmJobs j3 = {};
    j3.A[0] = p_ao;
    j3.W[0] = ow;
    j3.C[0] = out;
    j3.bias = ob;
    sgemm_nt<<<dim3(16, 32, 1), 256>>>(j3, B_DIM * S_DIM, E_DIM, E_DIM);
}

// round 3
// speedup vs baseline: 1.4879x; 1.4879x over previous
#include <cuda_runtime.h>
#include <cuda_bf16.h>
#include <math.h>
#include <stdint.h>

#define E_DIM 2048
#define B_DIM 2
#define S_DIM 2048
#define R_DIM 128
#define H_DIM 16
#define D_DIM 128
#define T_DIM (S_DIM + R_DIM)   /* 2176 */

// ---------------- scratch (static device allocations; no cudaMalloc) --------
__device__ __nv_bfloat16 g_wb[3][E_DIM * E_DIM];    // ternary weights (bf16 +-1/0)
__device__ __nv_bfloat16 g_xb[B_DIM * S_DIM * E_DIM]; // int8-valued activations (bf16)
__device__ float g_as[B_DIM * S_DIM];               // per-token 1/s dequant scale
__device__ float g_qp[B_DIM * S_DIM * E_DIM];       // Q projection
__device__ float g_kp[B_DIM * T_DIM * E_DIM];       // K (quant part + rk)
__device__ float g_vp[B_DIM * T_DIM * E_DIM];       // V (quant part + rv)
__device__ float g_ao[B_DIM * S_DIM * E_DIM];       // attention output
__device__ float g_part[3 * 1024];
__device__ float g_scales[3];

// ---------------- weight scale = mean(|w|) (deterministic 2-pass) ----------
__global__ void absmean_partial(const float* __restrict__ w,
                                float* __restrict__ part, int n) {
    __shared__ float red[256];
    int chunk = n / gridDim.x;
    int base = blockIdx.x * chunk;
    float s = 0.f;
    for (int i = threadIdx.x; i < chunk; i += blockDim.x) s += fabsf(w[base + i]);
    red[threadIdx.x] = s;
    __syncthreads();
    for (int off = 128; off > 0; off >>= 1) {
        if (threadIdx.x < off) red[threadIdx.x] += red[threadIdx.x + off];
        __syncthreads();
    }
    if (threadIdx.x == 0) part[blockIdx.x] = red[0];
}

__global__ void scale_finalize(const float* __restrict__ part,
                               float* __restrict__ scales, int nblk, float inv_n) {
    __shared__ float red[256];
    const float* p = part + blockIdx.x * nblk;
    float s = 0.f;
    for (int i = threadIdx.x; i < nblk; i += blockDim.x) s += p[i];
    red[threadIdx.x] = s;
    __syncthreads();
    for (int off = 128; off > 0; off >>= 1) {
        if (threadIdx.x < off) red[threadIdx.x] += red[threadIdx.x + off];
        __syncthreads();
    }
    if (threadIdx.x == 0) scales[blockIdx.x] = fmaxf(red[0] * inv_n, 1e-5f);
}

// ternary weight in bf16: t = clip(round(w/scale), -1, 1)   (exact in bf16)
__global__ void quant_weight_k(const float* __restrict__ w,
                               __nv_bfloat16* __restrict__ wb,
                               const float* __restrict__ scales, int sidx, int n) {
    float sc = scales[sidx];
    for (int i = blockIdx.x * blockDim.x + threadIdx.x; i < n;
         i += gridDim.x * blockDim.x) {
        float q = rintf(__fdiv_rn(w[i], sc));
        q = fminf(fmaxf(q, -1.f), 1.f);
        wb[i] = __float2bfloat16(q);
    }
}

// per-token absmax int8 quant: writes integer-valued bf16 + per-row 1/s
__global__ void quant_act_k(const float* __restrict__ x,
                            __nv_bfloat16* __restrict__ xb,
                            float* __restrict__ as_) {
    __shared__ float red[256];
    int row = blockIdx.x;
    const float* xr = x + (size_t)row * E_DIM;
    __nv_bfloat16* qr = xb + (size_t)row * E_DIM;
    float m = 0.f;
    for (int i = threadIdx.x; i < E_DIM; i += blockDim.x) m = fmaxf(m, fabsf(xr[i]));
    red[threadIdx.x] = m;
    __syncthreads();
    for (int off = 128; off > 0; off >>= 1) {
        if (threadIdx.x < off)
            red[threadIdx.x] = fmaxf(red[threadIdx.x], red[threadIdx.x + off]);
        __syncthreads();
    }
    float mx = fmaxf(red[0], 1e-5f);
    float s = __fdiv_rn(127.f, mx);
    if (threadIdx.x == 0) as_[row] = __fdiv_rn(1.f, s);
    for (int i = threadIdx.x; i < E_DIM; i += blockDim.x) {
        float q = rintf(xr[i] * s);
        q = fminf(fmaxf(q, -128.f), 127.f);
        qr[i] = __float2bfloat16(q);   // |q|<=128: exact in bf16
    }
}

// ---------------- bf16 tensor-core NT GEMM ---------------------------------
// C[M,N] = (A[M,K] @ W[N,K]^T) * rs[row] * (*ws)
// 128x128x64 tile, 256 thr (8 warps 4x2), mma.m16n8k16, SW128 smem, 2-stage.
struct BJobs {
    const __nv_bfloat16* A[6];
    const __nv_bfloat16* W[6];
    float* C[6];
    const float* rs[6];
    const float* ws[6];
};

__device__ __forceinline__ uint32_t swz(uint32_t o) { return o ^ ((o >> 3) & 0x70); }

__global__ __launch_bounds__(256, 1) void bgemm_nt(BJobs jobs, int M, int N, int K) {
    extern __shared__ __align__(128) char sm_raw[];
    int z = blockIdx.z;
    const __nv_bfloat16* A = jobs.A[z];
    const __nv_bfloat16* W = jobs.W[z];
    float* C = jobs.C[z];
    const float* rs = jobs.rs[z];
    const float* ws = jobs.ws[z];

    uint32_t sbase = (uint32_t)__cvta_generic_to_shared(sm_raw);
    int tid = threadIdx.x, lane = tid & 31, warp = tid >> 5;
    int wm = warp >> 1, wn = warp & 1;
    int bm = blockIdx.y * 128, bn = blockIdx.x * 128;

    const __nv_bfloat16* Ag = A + (size_t)bm * K;
    const __nv_bfloat16* Wg = W + (size_t)bn * K;

    float acc[2][8][4];
#pragma unroll
    for (int mf = 0; mf < 2; mf++)
#pragma unroll
        for (int nf = 0; nf < 8; nf++)
#pragma unroll
            for (int c = 0; c < 4; c++) acc[mf][nf][c] = 0.f;

    float4 sa[4], sw[4];
    // prologue: tile 0 -> regs -> smem stage 0
#pragma unroll
    for (int i = 0; i < 4; i++) {
        int idx = i * 256 + tid;
        int row = idx >> 3, c = idx & 7;
        sa[i] = *(const float4*)(Ag + (size_t)row * K + c * 8);
        sw[i] = *(const float4*)(Wg + (size_t)row * K + c * 8);
    }
#pragma unroll
    for (int i = 0; i < 4; i++) {
        int idx = i * 256 + tid;
        int row = idx >> 3, c = idx & 7;
        uint32_t off = swz((uint32_t)(row * 128 + c * 16));
        *(float4*)(sm_raw + off) = sa[i];
        *(float4*)(sm_raw + 16384 + off) = sw[i];
    }
    __syncthreads();

    int KT = K >> 6;
    for (int kt = 0; kt < KT; kt++) {
        int cur = kt & 1;
        if (kt + 1 < KT) {
#pragma unroll
            for (int i = 0; i < 4; i++) {
                int idx = i * 256 + tid;
                int row = idx >> 3, c = idx & 7;
                sa[i] = *(const float4*)(Ag + (size_t)row * K + (kt + 1) * 64 + c * 8);
                sw[i] = *(const float4*)(Wg + (size_t)row * K + (kt + 1) * 64 + c * 8);
            }
        }
        uint32_t abase = sbase + cur * 32768;
        uint32_t wbase = abase + 16384;
#pragma unroll
        for (int ks = 0; ks < 4; ks++) {
            uint32_t a[2][4];
#pragma unroll
            for (int mf = 0; mf < 2; mf++) {
                int r = wm * 32 + mf * 16 + ((lane >> 3) & 1) * 8 + (lane & 7);
                uint32_t off = swz((uint32_t)(r * 128 + ks * 32 + ((lane >> 4) & 1) * 16));
                uint32_t addr = abase + off;
                asm volatile(
                    "ldmatrix.sync.aligned.m8n8.x4.shared.b16 {%0,%1,%2,%3}, [%4];"
                    : "=r"(a[mf][0]), "=r"(a[mf][1]), "=r"(a[mf][2]), "=r"(a[mf][3])
                    : "r"(addr));
            }
            uint32_t b0[8], b1[8];
#pragma unroll
            for (int q = 0; q < 4; q++) {
                int r = wn * 64 + q * 16 + ((lane >> 3) & 1) * 8 + (lane & 7);
                uint32_t off = swz((uint32_t)(r * 128 + ks * 32 + ((lane >> 4) & 1) * 16));
                uint32_t addr = wbase + off;
                uint32_t r0, r1, r2, r3;
                asm volatile(
                    "ldmatrix.sync.aligned.m8n8.x4.shared.b16 {%0,%1,%2,%3}, [%4];"
                    : "=r"(r0), "=r"(r1), "=r"(r2), "=r"(r3)
                    : "r"(addr));
                b0[2 * q] = r0; b0[2 * q + 1] = r1;
                b1[2 * q] = r2; b1[2 * q + 1] = r3;
            }
#pragma unroll
            for (int mf = 0; mf < 2; mf++)
#pragma unroll
                for (int nf = 0; nf < 8; nf++)
                    asm volatile(
                        "mma.sync.aligned.m16n8k16.row.col.f32.bf16.bf16.f32 "
                        "{%0,%1,%2,%3},{%4,%5,%6,%7},{%8,%9},{%0,%1,%2,%3};"
                        : "+f"(acc[mf][nf][0]), "+f"(acc[mf][nf][1]),
                          "+f"(acc[mf][nf][2]), "+f"(acc[mf][nf][3])
                        : "r"(a[mf][0]), "r"(a[mf][1]), "r"(a[mf][2]), "r"(a[mf][3]),
                          "r"(b0[nf]), "r"(b1[nf]));
        }
        if (kt + 1 < KT) {
            int nxt = cur ^ 1;
#pragma unroll
            for (int i = 0; i < 4; i++) {
                int idx = i * 256 + tid;
                int row = idx >> 3, c = idx & 7;
                uint32_t off = swz((uint32_t)(row * 128 + c * 16));
                *(float4*)(sm_raw + nxt * 32768 + off) = sa[i];
                *(float4*)(sm_raw + nxt * 32768 + 16384 + off) = sw[i];
            }
        }
        __syncthreads();
    }

    // epilogue: scale + store
    int g = lane >> 2, t = lane & 3;
    float wsv = ws ? *ws : 1.f;
#pragma unroll
    for (int mf = 0; mf < 2; mf++) {
        int row0 = bm + wm * 32 + mf * 16 + g;
        float r0s = (rs ? rs[row0] : 1.f) * wsv;
        float r1s = (rs ? rs[row0 + 8] : 1.f) * wsv;
#pragma unroll
        for (int nf = 0; nf < 8; nf++) {
            int col = bn + wn * 64 + nf * 8 + 2 * t;
            float2 v0 = make_float2(acc[mf][nf][0] * r0s, acc[mf][nf][1] * r0s);
            float2 v1 = make_float2(acc[mf][nf][2] * r1s, acc[mf][nf][3] * r1s);
            *(float2*)&C[(size_t)row0 * N + col] = v0;
            *(float2*)&C[(size_t)(row0 + 8) * N + col] = v1;
        }
    }
}

// ---------------- fp32 NT SGEMM (rk/rv + out-proj) --------------------------
struct GemmJobs {
    const float* A[4];
    const float* W[4];
    float* C[4];
    const float* bias;
};

__global__ __launch_bounds__(256) void sgemm_nt(GemmJobs jobs, int M, int N, int K) {
    __shared__ __align__(16) float As[128][20];
    __shared__ __align__(16) float Ws[128][20];
    const float* A = jobs.A[blockIdx.z];
    const float* W = jobs.W[blockIdx.z];
    float* C = jobs.C[blockIdx.z];
    int tid = threadIdx.x;
    int tx = tid & 15, ty = tid >> 4;
    int bm = blockIdx.y * 128, bn = blockIdx.x * 128;

    float acc[8][8];
#pragma unroll
    for (int i = 0; i < 8; i++)
#pragma unroll
        for (int j = 0; j < 8; j++) acc[i][j] = 0.f;

    for (int kt = 0; kt < K; kt += 16) {
#pragma unroll
        for (int it = 0; it < 2; it++) {
            int idx = tid + it * 256;
            int row = idx >> 2, k4 = (idx & 3) * 4;
            *(float4*)&As[row][k4] =
                *(const float4*)&A[(size_t)(bm + row) * K + kt + k4];
            *(float4*)&Ws[row][k4] =
                *(const float4*)&W[(size_t)(bn + row) * K + kt + k4];
        }
        __syncthreads();
#pragma unroll
        for (int k4 = 0; k4 < 16; k4 += 4) {
            float4 a[8], b[8];
#pragma unroll
            for (int i = 0; i < 8; i++) a[i] = *(float4*)&As[ty + 16 * i][k4];
#pragma unroll
            for (int j = 0; j < 8; j++) b[j] = *(float4*)&Ws[tx + 16 * j][k4];
#pragma unroll
            for (int i = 0; i < 8; i++)
#pragma unroll
                for (int j = 0; j < 8; j++)
                    acc[i][j] += a[i].x * b[j].x + a[i].y * b[j].y +
                                 a[i].z * b[j].z + a[i].w * b[j].w;
        }
        __syncthreads();
    }

    const float* bias = jobs.bias;
#pragma unroll
    for (int i = 0; i < 8; i++) {
        int r = bm + ty + 16 * i;
#pragma unroll
        for (int j = 0; j < 8; j++) {
            int c = bn + tx + 16 * j;
            float v = acc[i][j];
            if (bias) v += bias[c];
            C[(size_t)r * N + c] = v;
        }
    }
}

// ---------------- flash attention, fp32, BQ=64, BK=64, D=128 ---------------
__global__ __launch_bounds__(256) void attn_k(const float* __restrict__ Q,
                                              const float* __restrict__ Kp,
                                              const float* __restrict__ Vp,
                                              float* __restrict__ O) {
    extern __shared__ float sm[];
    float* Qs  = sm;                  // [64][132]
    float* KVs = sm + 64 * 132;       // [64][132]
    float* Ss  = sm + 2 * 64 * 132;   // [64][68]
    float* mrow = Ss + 64 * 68;       // [64]
    float* lrow = mrow + 64;          // [64]
    float* arow = lrow + 64;          // [64]

    int tid = threadIdx.x;
    int tx = tid & 15, ty = tid >> 4;
    int q0 = blockIdx.x * 64;
    int h = blockIdx.y, b = blockIdx.z;

    const float* Qb = Q + ((size_t)b * S_DIM + q0) * E_DIM + h * D_DIM;
    const float* Kb = Kp + (size_t)b * T_DIM * E_DIM + h * D_DIM;
    const float* Vb = Vp + (size_t)b * T_DIM * E_DIM + h * D_DIM;

#pragma unroll
    for (int it = 0; it < 8; it++) {
        int idx = tid + it * 256;
        int r = idx >> 5, d4 = (idx & 31) * 4;
        *(float4*)&Qs[r * 132 + d4] = *(const float4*)&Qb[(size_t)r * E_DIM + d4];
    }
    if (tid < 64) { mrow[tid] = -1e30f; lrow[tid] = 0.f; }
    float o[4][8];
#pragma unroll
    for (int i = 0; i < 4; i++)
#pragma unroll
        for (int j = 0; j < 8; j++) o[i][j] = 0.f;
    __syncthreads();

    for (int t0 = 0; t0 < T_DIM; t0 += 64) {
#pragma unroll
        for (int it = 0; it < 8; it++) {
            int idx = tid + it * 256;
            int r = idx >> 5, d4 = (idx & 31) * 4;
            *(float4*)&KVs[r * 132 + d4] =
                *(const float4*)&Kb[(size_t)(t0 + r) * E_DIM + d4];
        }
        __syncthreads();

        float acc[4][4];
#pragma unroll
        for (int i = 0; i < 4; i++)
#pragma unroll
            for (int j = 0; j < 4; j++) acc[i][j] = 0.f;
#pragma unroll 4
        for (int d4 = 0; d4 < 128; d4 += 4) {
            float4 qv[4], kv[4];
#pragma unroll
            for (int i = 0; i < 4; i++)
                qv[i] = *(float4*)&Qs[(ty + 16 * i) * 132 + d4];
#pragma unroll
            for (int j = 0; j < 4; j++)
                kv[j] = *(float4*)&KVs[(tx + 16 * j) * 132 + d4];
#pragma unroll
            for (int i = 0; i < 4; i++)
#pragma unroll
                for (int j = 0; j < 4; j++)
                    acc[i][j] += qv[i].x * kv[j].x + qv[i].y * kv[j].y +
                                 qv[i].z * kv[j].z + qv[i].w * kv[j].w;
        }
        const float scl = 0.08838834764831845f;  // 1/sqrt(128)
#pragma unroll
        for (int i = 0; i < 4; i++)
#pragma unroll
            for (int j = 0; j < 4; j++)
                Ss[(ty + 16 * i) * 68 + tx + 16 * j] = acc[i][j] * scl;
        __syncthreads();

        {
            int r = tid >> 2;
            float* srow = Ss + r * 68 + (tid & 3) * 16;
            float mx = -1e30f;
#pragma unroll
            for (int c = 0; c < 16; c++) mx = fmaxf(mx, srow[c]);
            mx = fmaxf(mx, __shfl_xor_sync(0xffffffffu, mx, 1));
            mx = fmaxf(mx, __shfl_xor_sync(0xffffffffu, mx, 2));
            float mo = mrow[r];
            float mn = fmaxf(mo, mx);
            float al = __expf(mo - mn);
            float sum = 0.f;
#pragma unroll
            for (int c = 0; c < 16; c++) {
                float p = __expf(srow[c] - mn);
                srow[c] = p;
                sum += p;
            }
            sum += __shfl_xor_sync(0xffffffffu, sum, 1);
            sum += __shfl_xor_sync(0xffffffffu, sum, 2);
            if ((tid & 3) == 0) {
                mrow[r] = mn;
                arow[r] = al;
                lrow[r] = lrow[r] * al + sum;
            }
        }
        __syncthreads();

        float al4[4];
#pragma unroll
        for (int i = 0; i < 4; i++) al4[i] = arow[ty + 16 * i];
#pragma unroll
        for (int i = 0; i < 4; i++)
#pragma unroll
            for (int j = 0; j < 8; j++) o[i][j] *= al4[i];
#pragma unroll
        for (int it = 0; it < 8; it++) {
            int idx = tid + it * 256;
            int r = idx >> 5, d4 = (idx & 31) * 4;
            *(float4*)&KVs[r * 132 + d4] =
                *(const float4*)&Vb[(size_t)(t0 + r) * E_DIM + d4];
        }
        __syncthreads();

#pragma unroll 4
        for (int c = 0; c < 64; c++) {
            float p[4], v[8];
#pragma unroll
            for (int i = 0; i < 4; i++) p[i] = Ss[(ty + 16 * i) * 68 + c];
#pragma unroll
            for (int j = 0; j < 8; j++) v[j] = KVs[c * 132 + tx + 16 * j];
#pragma unroll
            for (int i = 0; i < 4; i++)
#pragma unroll
                for (int j = 0; j < 8; j++) o[i][j] += p[i] * v[j];
        }
        __syncthreads();
    }

    float li[4];
#pragma unroll
    for (int i = 0; i < 4; i++) li[i] = __fdiv_rn(1.f, lrow[ty + 16 * i]);
#pragma unroll
    for (int i = 0; i < 4; i++)
#pragma unroll
        for (int j = 0; j < 8; j++)
            O[((size_t)b * S_DIM + q0 + ty + 16 * i) * E_DIM + h * D_DIM + tx +
              16 * j] = o[i][j] * li[i];
}

// ---------------- launcher --------------------------------------------------
extern "C" void kernel_launch(void* const* d_in, const int* in_sizes, int n_in,
                              void* d_out, int out_size) {
    const float* x  = (const float*)d_in[0];
    const float* rt = (const float*)d_in[1];
    const float* qw = (const float*)d_in[2];
    const float* kw = (const float*)d_in[3];
    const float* vw = (const float*)d_in[4];
    const float* ow = (const float*)d_in[5];
    const float* ob = (const float*)d_in[6];
    float* out = (float*)d_out;

    __nv_bfloat16 *p_wb, *p_xb;
    float *p_as, *p_q, *p_k, *p_v, *p_ao, *p_part, *p_scales;
    cudaGetSymbolAddress((void**)&p_wb, g_wb);
    cudaGetSymbolAddress((void**)&p_xb, g_xb);
    cudaGetSymbolAddress((void**)&p_as, g_as);
    cudaGetSymbolAddress((void**)&p_q, g_qp);
    cudaGetSymbolAddress((void**)&p_k, g_kp);
    cudaGetSymbolAddress((void**)&p_v, g_vp);
    cudaGetSymbolAddress((void**)&p_ao, g_ao);
    cudaGetSymbolAddress((void**)&p_part, g_part);
    cudaGetSymbolAddress((void**)&p_scales, g_scales);

    const int n = E_DIM * E_DIM;

    // 1. ternary weight scales + bf16 ternary weights
    absmean_partial<<<1024, 256>>>(qw, p_part + 0 * 1024, n);
    absmean_partial<<<1024, 256>>>(kw, p_part + 1 * 1024, n);
    absmean_partial<<<1024, 256>>>(vw, p_part + 2 * 1024, n);
    scale_finalize<<<3, 256>>>(p_part, p_scales, 1024, 1.f / (float)n);
    quant_weight_k<<<2048, 256>>>(qw, p_wb + 0 * (size_t)n, p_scales, 0, n);
    quant_weight_k<<<2048, 256>>>(kw, p_wb + 1 * (size_t)n, p_scales, 1, n);
    quant_weight_k<<<2048, 256>>>(vw, p_wb + 2 * (size_t)n, p_scales, 2, n);

    // 2. per-token activation quant -> integer-valued bf16 + 1/s
    quant_act_k<<<B_DIM * S_DIM, 256>>>(x, p_xb, p_as);

    // 3. QKV projections: exact integer GEMM on bf16 tensor cores
    BJobs j1 = {};
    for (int z = 0; z < 6; z++) {
        int w = z >> 1, batch = z & 1;
        j1.A[z] = p_xb + (size_t)batch * S_DIM * E_DIM;
        j1.W[z] = p_wb + (size_t)w * n;
        if (w == 0)
            j1.C[z] = p_q + (size_t)batch * S_DIM * E_DIM;
        else if (w == 1)
            j1.C[z] = p_k + (size_t)batch * T_DIM * E_DIM;
        else
            j1.C[z] = p_v + (size_t)batch * T_DIM * E_DIM;
        j1.rs[z] = p_as + (size_t)batch * S_DIM;
        j1.ws[z] = p_scales + w;
    }
    cudaFuncSetAttribute(bgemm_nt, cudaFuncAttributeMaxDynamicSharedMemorySize,
                         65536);
    bgemm_nt<<<dim3(16, 16, 6), 256, 65536>>>(j1, S_DIM, E_DIM, E_DIM);

    // 4. reasoning rk/rv (UNquantized weights, fp32), appended at row S
    GemmJobs j2 = {};
    for (int z = 0; z < 4; z++) {
        int w = z >> 1, batch = z & 1;
        j2.A[z] = rt + (size_t)batch * R_DIM * E_DIM;
        j2.W[z] = (w == 0) ? kw : vw;
        j2.C[z] = ((w == 0) ? p_k : p_v) + (size_t)batch * T_DIM * E_DIM +
                  (size_t)S_DIM * E_DIM;
    }
    j2.bias = nullptr;
    sgemm_nt<<<dim3(16, 1, 4), 256>>>(j2, R_DIM, E_DIM, E_DIM);

    // 5. attention (fp32)
    const int ATT_SMEM = (2 * 64 * 132 + 64 * 68 + 3 * 64) * 4;  // 85760 B
    cudaFuncSetAttribute(attn_k, cudaFuncAttributeMaxDynamicSharedMemorySize,
                         ATT_SMEM);
    attn_k<<<dim3(S_DIM / 64, H_DIM, B_DIM), 256, ATT_SMEM>>>(p_q, p_k, p_v, p_ao);

    // 6. output projection + bias (fp32)
    GemmJobs j3 = {};
    j3.A[0] = p_ao;
    j3.W[0] = ow;
    j3.C[0] = out;
    j3.bias = ob;
    sgemm_nt<<<dim3(16, 32, 1), 256>>>(j3, B_DIM * S_DIM, E_DIM, E_DIM);
}

// round 4
// speedup vs baseline: 1.9464x; 1.3081x over previous
#include <cuda_runtime.h>
#include <cuda_bf16.h>
#include <math.h>
#include <stdint.h>

#define E_DIM 2048
#define B_DIM 2
#define S_DIM 2048
#define R_DIM 128
#define H_DIM 16
#define D_DIM 128
#define T_DIM (S_DIM + R_DIM)   /* 2176 */
#define KCAT (3 * E_DIM)        /* 6144: [hi|lo|hi] split concat */

// ---------------- scratch (static device allocations) ----------------------
__device__ __nv_bfloat16 g_wb[3][E_DIM * E_DIM];      // ternary weights bf16
__device__ __nv_bfloat16 g_xb[B_DIM * S_DIM * E_DIM]; // int8-valued acts bf16
__device__ float g_as[B_DIM * S_DIM];                 // per-token 1/s
__device__ float g_qp[B_DIM * S_DIM * E_DIM];         // Q
__device__ float g_kp[B_DIM * T_DIM * E_DIM];         // K (+rk)
__device__ float g_vp[B_DIM * T_DIM * E_DIM];         // V (+rv)
__device__ __nv_bfloat16 g_acat[(size_t)B_DIM * S_DIM * KCAT]; // [AOh|AOl|AOh]
__device__ __nv_bfloat16 g_wcat[(size_t)E_DIM * KCAT];         // [OWh|OWh|OWl]
__device__ float g_part[3 * 1024];
__device__ float g_scales[3];

// ---------------- weight scale = mean(|w|) ----------------------------------
__global__ void absmean_partial(const float* __restrict__ w,
                                float* __restrict__ part, int n) {
    __shared__ float red[256];
    int chunk = n / gridDim.x;
    int base = blockIdx.x * chunk;
    float s = 0.f;
    for (int i = threadIdx.x; i < chunk; i += blockDim.x) s += fabsf(w[base + i]);
    red[threadIdx.x] = s;
    __syncthreads();
    for (int off = 128; off > 0; off >>= 1) {
        if (threadIdx.x < off) red[threadIdx.x] += red[threadIdx.x + off];
        __syncthreads();
    }
    if (threadIdx.x == 0) part[blockIdx.x] = red[0];
}

__global__ void scale_finalize(const float* __restrict__ part,
                               float* __restrict__ scales, int nblk, float inv_n) {
    __shared__ float red[256];
    const float* p = part + blockIdx.x * nblk;
    float s = 0.f;
    for (int i = threadIdx.x; i < nblk; i += blockDim.x) s += p[i];
    red[threadIdx.x] = s;
    __syncthreads();
    for (int off = 128; off > 0; off >>= 1) {
        if (threadIdx.x < off) red[threadIdx.x] += red[threadIdx.x + off];
        __syncthreads();
    }
    if (threadIdx.x == 0) scales[blockIdx.x] = fmaxf(red[0] * inv_n, 1e-5f);
}

__global__ void quant_weight_k(const float* __restrict__ w,
                               __nv_bfloat16* __restrict__ wb,
                               const float* __restrict__ scales, int sidx, int n) {
    float sc = scales[sidx];
    for (int i = blockIdx.x * blockDim.x + threadIdx.x; i < n;
         i += gridDim.x * blockDim.x) {
        float q = rintf(__fdiv_rn(w[i], sc));
        q = fminf(fmaxf(q, -1.f), 1.f);
        wb[i] = __float2bfloat16(q);
    }
}

__global__ void quant_act_k(const float* __restrict__ x,
                            __nv_bfloat16* __restrict__ xb,
                            float* __restrict__ as_) {
    __shared__ float red[256];
    int row = blockIdx.x;
    const float* xr = x + (size_t)row * E_DIM;
    __nv_bfloat16* qr = xb + (size_t)row * E_DIM;
    float m = 0.f;
    for (int i = threadIdx.x; i < E_DIM; i += blockDim.x) m = fmaxf(m, fabsf(xr[i]));
    red[threadIdx.x] = m;
    __syncthreads();
    for (int off = 128; off > 0; off >>= 1) {
        if (threadIdx.x < off)
            red[threadIdx.x] = fmaxf(red[threadIdx.x], red[threadIdx.x + off]);
        __syncthreads();
    }
    float mx = fmaxf(red[0], 1e-5f);
    float s = __fdiv_rn(127.f, mx);
    if (threadIdx.x == 0) as_[row] = __fdiv_rn(1.f, s);
    for (int i = threadIdx.x; i < E_DIM; i += blockDim.x) {
        float q = rintf(xr[i] * s);
        q = fminf(fmaxf(q, -128.f), 127.f);
        qr[i] = __float2bfloat16(q);
    }
}

// build [Wh|Wh|Wl] concat for out_w (row-major [E, 3E])
__global__ void wsplit_k(const float* __restrict__ w,
                         __nv_bfloat16* __restrict__ wc) {
    int idx = blockIdx.x * blockDim.x + threadIdx.x;
    if (idx >= E_DIM * E_DIM) return;
    int r = idx / E_DIM, c = idx % E_DIM;
    float x = w[idx];
    __nv_bfloat16 h = __float2bfloat16(x);
    __nv_bfloat16 l = __float2bfloat16(x - __bfloat162float(h));
    size_t base = (size_t)r * KCAT + c;
    wc[base] = h;
    wc[base + E_DIM] = h;
    wc[base + 2 * E_DIM] = l;
}

// ---------------- bf16 tensor-core NT GEMM ---------------------------------
struct BJobs {
    const __nv_bfloat16* A[6];
    const __nv_bfloat16* W[6];
    float* C[6];
    const float* rs[6];
    const float* ws[6];
    const float* bias;
};

__device__ __forceinline__ uint32_t swz(uint32_t o) { return o ^ ((o >> 3) & 0x70); }

__global__ __launch_bounds__(256, 1) void bgemm_nt(BJobs jobs, int M, int N, int K) {
    extern __shared__ __align__(128) char sm_raw[];
    int z = blockIdx.z;
    const __nv_bfloat16* A = jobs.A[z];
    const __nv_bfloat16* W = jobs.W[z];
    float* C = jobs.C[z];
    const float* rs = jobs.rs[z];
    const float* ws = jobs.ws[z];

    uint32_t sbase = (uint32_t)__cvta_generic_to_shared(sm_raw);
    int tid = threadIdx.x, lane = tid & 31, warp = tid >> 5;
    int wm = warp >> 1, wn = warp & 1;
    int bm = blockIdx.y * 128, bn = blockIdx.x * 128;

    const __nv_bfloat16* Ag = A + (size_t)bm * K;
    const __nv_bfloat16* Wg = W + (size_t)bn * K;

    float acc[2][8][4];
#pragma unroll
    for (int mf = 0; mf < 2; mf++)
#pragma unroll
        for (int nf = 0; nf < 8; nf++)
#pragma unroll
            for (int c = 0; c < 4; c++) acc[mf][nf][c] = 0.f;

    float4 sa[4], sw[4];
#pragma unroll
    for (int i = 0; i < 4; i++) {
        int idx = i * 256 + tid;
        int row = idx >> 3, c = idx & 7;
        sa[i] = *(const float4*)(Ag + (size_t)row * K + c * 8);
        sw[i] = *(const float4*)(Wg + (size_t)row * K + c * 8);
    }
#pragma unroll
    for (int i = 0; i < 4; i++) {
        int idx = i * 256 + tid;
        int row = idx >> 3, c = idx & 7;
        uint32_t off = swz((uint32_t)(row * 128 + c * 16));
        *(float4*)(sm_raw + off) = sa[i];
        *(float4*)(sm_raw + 16384 + off) = sw[i];
    }
    __syncthreads();

    int KT = K >> 6;
    for (int kt = 0; kt < KT; kt++) {
        int cur = kt & 1;
        if (kt + 1 < KT) {
#pragma unroll
            for (int i = 0; i < 4; i++) {
                int idx = i * 256 + tid;
                int row = idx >> 3, c = idx & 7;
                sa[i] = *(const float4*)(Ag + (size_t)row * K + (kt + 1) * 64 + c * 8);
                sw[i] = *(const float4*)(Wg + (size_t)row * K + (kt + 1) * 64 + c * 8);
            }
        }
        uint32_t abase = sbase + cur * 32768;
        uint32_t wbase = abase + 16384;
#pragma unroll
        for (int ks = 0; ks < 4; ks++) {
            uint32_t a[2][4];
#pragma unroll
            for (int mf = 0; mf < 2; mf++) {
                int r = wm * 32 + mf * 16 + ((lane >> 3) & 1) * 8 + (lane & 7);
                uint32_t off = swz((uint32_t)(r * 128 + ks * 32 + ((lane >> 4) & 1) * 16));
                uint32_t addr = abase + off;
                asm volatile(
                    "ldmatrix.sync.aligned.m8n8.x4.shared.b16 {%0,%1,%2,%3}, [%4];"
                    : "=r"(a[mf][0]), "=r"(a[mf][1]), "=r"(a[mf][2]), "=r"(a[mf][3])
                    : "r"(addr));
            }
            uint32_t b0[8], b1[8];
#pragma unroll
            for (int q = 0; q < 4; q++) {
                int r = wn * 64 + q * 16 + ((lane >> 3) & 1) * 8 + (lane & 7);
                uint32_t off = swz((uint32_t)(r * 128 + ks * 32 + ((lane >> 4) & 1) * 16));
                uint32_t addr = wbase + off;
                uint32_t r0, r1, r2, r3;
                asm volatile(
                    "ldmatrix.sync.aligned.m8n8.x4.shared.b16 {%0,%1,%2,%3}, [%4];"
                    : "=r"(r0), "=r"(r1), "=r"(r2), "=r"(r3)
                    : "r"(addr));
                b0[2 * q] = r0; b0[2 * q + 1] = r1;
                b1[2 * q] = r2; b1[2 * q + 1] = r3;
            }
#pragma unroll
            for (int mf = 0; mf < 2; mf++)
#pragma unroll
                for (int nf = 0; nf < 8; nf++)
                    asm volatile(
                        "mma.sync.aligned.m16n8k16.row.col.f32.bf16.bf16.f32 "
                        "{%0,%1,%2,%3},{%4,%5,%6,%7},{%8,%9},{%0,%1,%2,%3};"
                        : "+f"(acc[mf][nf][0]), "+f"(acc[mf][nf][1]),
                          "+f"(acc[mf][nf][2]), "+f"(acc[mf][nf][3])
                        : "r"(a[mf][0]), "r"(a[mf][1]), "r"(a[mf][2]), "r"(a[mf][3]),
                          "r"(b0[nf]), "r"(b1[nf]));
        }
        if (kt + 1 < KT) {
            int nxt = cur ^ 1;
#pragma unroll
            for (int i = 0; i < 4; i++) {
                int idx = i * 256 + tid;
                int row = idx >> 3, c = idx & 7;
                uint32_t off = swz((uint32_t)(row * 128 + c * 16));
                *(float4*)(sm_raw + nxt * 32768 + off) = sa[i];
                *(float4*)(sm_raw + nxt * 32768 + 16384 + off) = sw[i];
            }
        }
        __syncthreads();
    }

    int g = lane >> 2, t = lane & 3;
    float wsv = ws ? *ws : 1.f;
    const float* bias = jobs.bias;
#pragma unroll
    for (int mf = 0; mf < 2; mf++) {
        int row0 = bm + wm * 32 + mf * 16 + g;
        float r0s = (rs ? rs[row0] : 1.f) * wsv;
        float r1s = (rs ? rs[row0 + 8] : 1.f) * wsv;
#pragma unroll
        for (int nf = 0; nf < 8; nf++) {
            int col = bn + wn * 64 + nf * 8 + 2 * t;
            float b0v = bias ? bias[col] : 0.f;
            float b1v = bias ? bias[col + 1] : 0.f;
            float2 v0 = make_float2(acc[mf][nf][0] * r0s + b0v,
                                    acc[mf][nf][1] * r0s + b1v);
            float2 v1 = make_float2(acc[mf][nf][2] * r1s + b0v,
                                    acc[mf][nf][3] * r1s + b1v);
            *(float2*)&C[(size_t)row0 * N + col] = v0;
            *(float2*)&C[(size_t)(row0 + 8) * N + col] = v1;
        }
    }
}

// ---------------- fp32 NT SGEMM 128x64 tile (rk/rv) -------------------------
struct GemmJobs {
    const float* A[4];
    const float* W[4];
    float* C[4];
};

__global__ __launch_bounds__(256) void sgemm_nt64(GemmJobs jobs, int M, int N, int K) {
    __shared__ __align__(16) float As[128][20];
    __shared__ __align__(16) float Ws[64][20];
    const float* A = jobs.A[blockIdx.z];
    const float* W = jobs.W[blockIdx.z];
    float* C = jobs.C[blockIdx.z];
    int tid = threadIdx.x;
    int tx = tid & 15, ty = tid >> 4;
    int bn = blockIdx.x * 64;

    float acc[8][4];
#pragma unroll
    for (int i = 0; i < 8; i++)
#pragma unroll
        for (int j = 0; j < 4; j++) acc[i][j] = 0.f;

    for (int kt = 0; kt < K; kt += 16) {
#pragma unroll
        for (int it = 0; it < 2; it++) {
            int idx = tid + it * 256;
            int row = idx >> 2, k4 = (idx & 3) * 4;
            *(float4*)&As[row][k4] =
                *(const float4*)&A[(size_t)row * K + kt + k4];
        }
        {
            int row = tid >> 2, k4 = (tid & 3) * 4;
            *(float4*)&Ws[row][k4] =
                *(const float4*)&W[(size_t)(bn + row) * K + kt + k4];
        }
        __syncthreads();
#pragma unroll
        for (int k4 = 0; k4 < 16; k4 += 4) {
            float4 a[8], b[4];
#pragma unroll
            for (int i = 0; i < 8; i++) a[i] = *(float4*)&As[ty + 16 * i][k4];
#pragma unroll
            for (int j = 0; j < 4; j++) b[j] = *(float4*)&Ws[tx + 16 * j][k4];
#pragma unroll
            for (int i = 0; i < 8; i++)
#pragma unroll
                for (int j = 0; j < 4; j++)
                    acc[i][j] += a[i].x * b[j].x + a[i].y * b[j].y +
                                 a[i].z * b[j].z + a[i].w * b[j].w;
        }
        __syncthreads();
    }
#pragma unroll
    for (int i = 0; i < 8; i++) {
        int r = ty + 16 * i;
#pragma unroll
        for (int j = 0; j < 4; j++) C[(size_t)r * N + bn + tx + 16 * j] = acc[i][j];
    }
}

// ---------------- tensor-core flash attention (bf16 hi/lo split) ------------
// BQ=128, BK=64, D=128, 256 threads (8 warps, warp w owns q-rows [w*16,+16)).
// Writes output directly as [AOh|AOl|AOh] bf16 concat rows of g_acat.
#define ATT_Q_OFF 0                          /* [128][256] bf16, 512B rows */
#define ATT_K_OFF 65536                      /* [64][256]  bf16 */
#define ATT_V_OFF 98304                      /* [128][128] bf16: [Vh;Vl], 256B rows */
#define ATT_P_OFF 131072                     /* [128][128] bf16: [Ph|Pl] */
#define ATT_S_OFF 163840                     /* [128][68] fp32 */
#define ATT_M_OFF (163840 + 128 * 68 * 4)    /* 198656 */
#define ATT_L_OFF (ATT_M_OFF + 512)
#define ATT_A_OFF (ATT_L_OFF + 512)
#define ATT_SMEM (ATT_A_OFF + 512)           /* 200192 bytes */

__device__ __forceinline__ uint32_t sw512o(int r, int c) {
    return (uint32_t)(r * 512 + ((((c >> 3) ^ (r & 7))) << 4) + ((c & 7) << 1));
}
__device__ __forceinline__ uint32_t sw256o(int r, int c) {
    return (uint32_t)(r * 256 + ((((c >> 3) ^ (r & 7))) << 4) + ((c & 7) << 1));
}
__device__ __forceinline__ void ldsm4(uint32_t addr, uint32_t& r0, uint32_t& r1,
                                      uint32_t& r2, uint32_t& r3) {
    asm volatile("ldmatrix.sync.aligned.m8n8.x4.shared.b16 {%0,%1,%2,%3}, [%4];"
                 : "=r"(r0), "=r"(r1), "=r"(r2), "=r"(r3) : "r"(addr));
}
__device__ __forceinline__ void ldsm4t(uint32_t addr, uint32_t& r0, uint32_t& r1,
                                       uint32_t& r2, uint32_t& r3) {
    asm volatile("ldmatrix.sync.aligned.m8n8.x4.trans.shared.b16 {%0,%1,%2,%3}, [%4];"
                 : "=r"(r0), "=r"(r1), "=r"(r2), "=r"(r3) : "r"(addr));
}

__global__ __launch_bounds__(256, 1) void attn_tc(const float* __restrict__ Q,
                                                  const float* __restrict__ Kp,
                                                  const float* __restrict__ Vp,
                                                  __nv_bfloat16* __restrict__ AOcat) {
    extern __shared__ __align__(128) char smc[];
    uint32_t sb = (uint32_t)__cvta_generic_to_shared(smc);
    float* Ssf = (float*)(smc + ATT_S_OFF);
    float* mrow = (float*)(smc + ATT_M_OFF);
    float* lrow = (float*)(smc + ATT_L_OFF);
    float* arow = (float*)(smc + ATT_A_OFF);

    int tid = threadIdx.x, lane = tid & 31, w = tid >> 5;
    int q0 = blockIdx.x * 128;
    int h = blockIdx.y, b = blockIdx.z;

    const float* Qg = Q + ((size_t)(b * S_DIM + q0)) * E_DIM + h * D_DIM;
    const float* Kg = Kp + (size_t)b * T_DIM * E_DIM + h * D_DIM;
    const float* Vg = Vp + (size_t)b * T_DIM * E_DIM + h * D_DIM;

    // load Q, split hi/lo
#pragma unroll
    for (int it = 0; it < 16; it++) {
        int idx = it * 256 + tid;
        int r = idx >> 5, d4 = (idx & 31) * 4;
        float4 v = *(const float4*)&Qg[(size_t)r * E_DIM + d4];
        __nv_bfloat162 h01 = __floats2bfloat162_rn(v.x, v.y);
        __nv_bfloat162 h23 = __floats2bfloat162_rn(v.z, v.w);
        __nv_bfloat162 l01 = __floats2bfloat162_rn(v.x - __bfloat162float(h01.x),
                                                   v.y - __bfloat162float(h01.y));
        __nv_bfloat162 l23 = __floats2bfloat162_rn(v.z - __bfloat162float(h23.x),
                                                   v.w - __bfloat162float(h23.y));
        *(__nv_bfloat162*)(smc + ATT_Q_OFF + sw512o(r, d4)) = h01;
        *(__nv_bfloat162*)(smc + ATT_Q_OFF + sw512o(r, d4 + 2)) = h23;
        *(__nv_bfloat162*)(smc + ATT_Q_OFF + sw512o(r, 128 + d4)) = l01;
        *(__nv_bfloat162*)(smc + ATT_Q_OFF + sw512o(r, 128 + d4 + 2)) = l23;
    }
    if (tid < 128) { mrow[tid] = -1e30f; lrow[tid] = 0.f; }

    float o[16][4];
#pragma unroll
    for (int nf = 0; nf < 16; nf++)
#pragma unroll
        for (int c = 0; c < 4; c++) o[nf][c] = 0.f;
    __syncthreads();

    const float scl = 0.08838834764831845f;  // 1/sqrt(128)

    for (int t0 = 0; t0 < T_DIM; t0 += 64) {
        // phase 1: K tile -> smem split
#pragma unroll
        for (int it = 0; it < 8; it++) {
            int idx = it * 256 + tid;
            int r = idx >> 5, d4 = (idx & 31) * 4;
            float4 v = *(const float4*)&Kg[(size_t)(t0 + r) * E_DIM + d4];
            __nv_bfloat162 h01 = __floats2bfloat162_rn(v.x, v.y);
            __nv_bfloat162 h23 = __floats2bfloat162_rn(v.z, v.w);
            __nv_bfloat162 l01 = __floats2bfloat162_rn(v.x - __bfloat162float(h01.x),
                                                       v.y - __bfloat162float(h01.y));
            __nv_bfloat162 l23 = __floats2bfloat162_rn(v.z - __bfloat162float(h23.x),
                                                       v.w - __bfloat162float(h23.y));
            *(__nv_bfloat162*)(smc + ATT_K_OFF + sw512o(r, d4)) = h01;
            *(__nv_bfloat162*)(smc + ATT_K_OFF + sw512o(r, d4 + 2)) = h23;
            *(__nv_bfloat162*)(smc + ATT_K_OFF + sw512o(r, 128 + d4)) = l01;
            *(__nv_bfloat162*)(smc + ATT_K_OFF + sw512o(r, 128 + d4 + 2)) = l23;
        }
        __syncthreads();

        // phase 2: S = Qcat @ Kcat^T (3-term split, 24 k16 steps)
        float accs[8][4];
#pragma unroll
        for (int nf = 0; nf < 8; nf++)
#pragma unroll
            for (int c = 0; c < 4; c++) accs[nf][c] = 0.f;

#pragma unroll
        for (int s = 0; s < 24; s++) {
            int aoff = (s < 8) ? s * 16 : (s < 16) ? 128 + (s - 8) * 16 : (s - 16) * 16;
            int boff = (s < 8) ? s * 16 : (s < 16) ? (s - 8) * 16 : 128 + (s - 16) * 16;
            uint32_t a0, a1, a2, a3;
            {
                int ar = w * 16 + ((lane >> 3) & 1) * 8 + (lane & 7);
                int ac = aoff + ((lane >> 4) & 1) * 8;
                ldsm4(sb + ATT_Q_OFF + sw512o(ar, ac), a0, a1, a2, a3);
            }
            uint32_t b0[8], b1[8];
#pragma unroll
            for (int nb = 0; nb < 4; nb++) {
                int br = nb * 16 + ((lane >> 3) & 1) * 8 + (lane & 7);
                int bc = boff + ((lane >> 4) & 1) * 8;
                uint32_t r0, r1, r2, r3;
                ldsm4(sb + ATT_K_OFF + sw512o(br, bc), r0, r1, r2, r3);
                b0[2 * nb] = r0; b0[2 * nb + 1] = r1;
                b1[2 * nb] = r2; b1[2 * nb + 1] = r3;
            }
#pragma unroll
            for (int nf = 0; nf < 8; nf++)
                asm volatile(
                    "mma.sync.aligned.m16n8k16.row.col.f32.bf16.bf16.f32 "
                    "{%0,%1,%2,%3},{%4,%5,%6,%7},{%8,%9},{%0,%1,%2,%3};"
                    : "+f"(accs[nf][0]), "+f"(accs[nf][1]),
                      "+f"(accs[nf][2]), "+f"(accs[nf][3])
                    : "r"(a0), "r"(a1), "r"(a2), "r"(a3),
                      "r"(b0[nf]), "r"(b1[nf]));
        }

        // phase 3: scores -> smem fp32
        {
            int g = lane >> 2, t = lane & 3;
            int row0 = w * 16 + g;
#pragma unroll
            for (int nf = 0; nf < 8; nf++) {
                int col = nf * 8 + 2 * t;
                *(float2*)&Ssf[row0 * 68 + col] =
                    make_float2(accs[nf][0] * scl, accs[nf][1] * scl);
                *(float2*)&Ssf[(row0 + 8) * 68 + col] =
                    make_float2(accs[nf][2] * scl, accs[nf][3] * scl);
            }
        }
        __syncthreads();

        // phase 4: online softmax (2 threads/row), write Ph|Pl
        {
            int r = tid >> 1, half = tid & 1;
            const float* srow = Ssf + r * 68 + half * 32;
            float mx = -1e30f;
#pragma unroll
            for (int j = 0; j < 32; j++) mx = fmaxf(mx, srow[j]);
            mx = fmaxf(mx, __shfl_xor_sync(0xffffffffu, mx, 1));
            float mo = mrow[r];
            float mn = fmaxf(mo, mx);
            float al = __expf(mo - mn);
            float sum = 0.f;
#pragma unroll
            for (int j = 0; j < 32; j += 2) {
                float p0 = __expf(srow[j] - mn);
                float p1 = __expf(srow[j + 1] - mn);
                sum += p0 + p1;
                __nv_bfloat162 ph = __floats2bfloat162_rn(p0, p1);
                __nv_bfloat162 pl =
                    __floats2bfloat162_rn(p0 - __bfloat162float(ph.x),
                                          p1 - __bfloat162float(ph.y));
                int c = half * 32 + j;
                *(__nv_bfloat162*)(smc + ATT_P_OFF + sw256o(r, c)) = ph;
                *(__nv_bfloat162*)(smc + ATT_P_OFF + sw256o(r, 64 + c)) = pl;
            }
            sum += __shfl_xor_sync(0xffffffffu, sum, 1);
            if (half == 0) {
                mrow[r] = mn;
                arow[r] = al;
                lrow[r] = lrow[r] * al + sum;
            }
        }
        __syncthreads();

        // phase 5: rescale o, load V tile split
        {
            int g = lane >> 2;
            float a0v = arow[w * 16 + g];
            float a8v = arow[w * 16 + 8 + g];
#pragma unroll
            for (int nf = 0; nf < 16; nf++) {
                o[nf][0] *= a0v; o[nf][1] *= a0v;
                o[nf][2] *= a8v; o[nf][3] *= a8v;
            }
        }
#pragma unroll
        for (int it = 0; it < 8; it++) {
            int idx = it * 256 + tid;
            int r = idx >> 5, d4 = (idx & 31) * 4;
            float4 v = *(const float4*)&Vg[(size_t)(t0 + r) * E_DIM + d4];
            __nv_bfloat162 h01 = __floats2bfloat162_rn(v.x, v.y);
            __nv_bfloat162 h23 = __floats2bfloat162_rn(v.z, v.w);
            __nv_bfloat162 l01 = __floats2bfloat162_rn(v.x - __bfloat162float(h01.x),
                                                       v.y - __bfloat162float(h01.y));
            __nv_bfloat162 l23 = __floats2bfloat162_rn(v.z - __bfloat162float(h23.x),
                                                       v.w - __bfloat162float(h23.y));
            *(__nv_bfloat162*)(smc + ATT_V_OFF + sw256o(r, d4)) = h01;
            *(__nv_bfloat162*)(smc + ATT_V_OFF + sw256o(r, d4 + 2)) = h23;
            *(__nv_bfloat162*)(smc + ATT_V_OFF + sw256o(64 + r, d4)) = l01;
            *(__nv_bfloat162*)(smc + ATT_V_OFF + sw256o(64 + r, d4 + 2)) = l23;
        }
        __syncthreads();

        // phase 6: o += Pcat @ Vcat (3-term, 12 k16 steps)
#pragma unroll
        for (int s = 0; s < 12; s++) {
            int pcol = (s < 4) ? s * 16 : (s < 8) ? 64 + (s - 4) * 16 : (s - 8) * 16;
            int vrow = (s < 4) ? s * 16 : (s < 8) ? (s - 4) * 16 : 64 + (s - 8) * 16;
            uint32_t a0, a1, a2, a3;
            {
                int ar = w * 16 + ((lane >> 3) & 1) * 8 + (lane & 7);
                int ac = pcol + ((lane >> 4) & 1) * 8;
                ldsm4(sb + ATT_P_OFF + sw256o(ar, ac), a0, a1, a2, a3);
            }
#pragma unroll
            for (int ng = 0; ng < 8; ng++) {
                int vr = vrow + ((lane >> 3) & 1) * 8 + (lane & 7);
                int vc = ng * 16 + ((lane >> 4) & 1) * 8;
                uint32_t r0, r1, r2, r3;
                ldsm4t(sb + ATT_V_OFF + sw256o(vr, vc), r0, r1, r2, r3);
                asm volatile(
                    "mma.sync.aligned.m16n8k16.row.col.f32.bf16.bf16.f32 "
                    "{%0,%1,%2,%3},{%4,%5,%6,%7},{%8,%9},{%0,%1,%2,%3};"
                    : "+f"(o[2 * ng][0]), "+f"(o[2 * ng][1]),
                      "+f"(o[2 * ng][2]), "+f"(o[2 * ng][3])
                    : "r"(a0), "r"(a1), "r"(a2), "r"(a3), "r"(r0), "r"(r1));
                asm volatile(
                    "mma.sync.aligned.m16n8k16.row.col.f32.bf16.bf16.f32 "
                    "{%0,%1,%2,%3},{%4,%5,%6,%7},{%8,%9},{%0,%1,%2,%3};"
                    : "+f"(o[2 * ng + 1][0]), "+f"(o[2 * ng + 1][1]),
                      "+f"(o[2 * ng + 1][2]), "+f"(o[2 * ng + 1][3])
                    : "r"(a0), "r"(a1), "r"(a2), "r"(a3), "r"(r2), "r"(r3));
            }
        }
        __syncthreads();
    }

    // epilogue: normalize and write hi/lo concat rows of AOcat
    {
        int g = lane >> 2, t = lane & 3;
        int r0 = w * 16 + g;
        float li0 = __fdiv_rn(1.f, lrow[r0]);
        float li8 = __fdiv_rn(1.f, lrow[r0 + 8]);
        size_t grow0 = (size_t)(b * S_DIM + q0 + r0) * KCAT + h * D_DIM;
        size_t grow8 = grow0 + (size_t)8 * KCAT;
#pragma unroll
        for (int nf = 0; nf < 16; nf++) {
            int c = nf * 8 + 2 * t;
            float f0 = o[nf][0] * li0, f1 = o[nf][1] * li0;
            float f2 = o[nf][2] * li8, f3 = o[nf][3] * li8;
            __nv_bfloat162 h0 = __floats2bfloat162_rn(f0, f1);
            __nv_bfloat162 l0 = __floats2bfloat162_rn(f0 - __bfloat162float(h0.x),
                                                      f1 - __bfloat162float(h0.y));
            __nv_bfloat162 h8 = __floats2bfloat162_rn(f2, f3);
            __nv_bfloat162 l8 = __floats2bfloat162_rn(f2 - __bfloat162float(h8.x),
                                                      f3 - __bfloat162float(h8.y));
            *(__nv_bfloat162*)&AOcat[grow0 + c] = h0;
            *(__nv_bfloat162*)&AOcat[grow0 + E_DIM + c] = l0;
            *(__nv_bfloat162*)&AOcat[grow0 + 2 * E_DIM + c] = h0;
            *(__nv_bfloat162*)&AOcat[grow8 + c] = h8;
            *(__nv_bfloat162*)&AOcat[grow8 + E_DIM + c] = l8;
            *(__nv_bfloat162*)&AOcat[grow8 + 2 * E_DIM + c] = h8;
        }
    }
}

// ---------------- launcher --------------------------------------------------
extern "C" void kernel_launch(void* const* d_in, const int* in_sizes, int n_in,
                              void* d_out, int out_size) {
    const float* x  = (const float*)d_in[0];
    const float* rt = (const float*)d_in[1];
    const float* qw = (const float*)d_in[2];
    const float* kw = (const float*)d_in[3];
    const float* vw = (const float*)d_in[4];
    const float* ow = (const float*)d_in[5];
    const float* ob = (const float*)d_in[6];
    float* out = (float*)d_out;

    __nv_bfloat16 *p_wb, *p_xb, *p_acat, *p_wcat;
    float *p_as, *p_q, *p_k, *p_v, *p_part, *p_scales;
    cudaGetSymbolAddress((void**)&p_wb, g_wb);
    cudaGetSymbolAddress((void**)&p_xb, g_xb);
    cudaGetSymbolAddress((void**)&p_as, g_as);
    cudaGetSymbolAddress((void**)&p_q, g_qp);
    cudaGetSymbolAddress((void**)&p_k, g_kp);
    cudaGetSymbolAddress((void**)&p_v, g_vp);
    cudaGetSymbolAddress((void**)&p_acat, g_acat);
    cudaGetSymbolAddress((void**)&p_wcat, g_wcat);
    cudaGetSymbolAddress((void**)&p_part, g_part);
    cudaGetSymbolAddress((void**)&p_scales, g_scales);

    const int n = E_DIM * E_DIM;

    // 1. ternary weight scales + bf16 ternary weights
    absmean_partial<<<1024, 256>>>(qw, p_part + 0 * 1024, n);
    absmean_partial<<<1024, 256>>>(kw, p_part + 1 * 1024, n);
    absmean_partial<<<1024, 256>>>(vw, p_part + 2 * 1024, n);
    scale_finalize<<<3, 256>>>(p_part, p_scales, 1024, 1.f / (float)n);
    quant_weight_k<<<2048, 256>>>(qw, p_wb + 0 * (size_t)n, p_scales, 0, n);
    quant_weight_k<<<2048, 256>>>(kw, p_wb + 1 * (size_t)n, p_scales, 1, n);
    quant_weight_k<<<2048, 256>>>(vw, p_wb + 2 * (size_t)n, p_scales, 2, n);

    // 2. per-token activation quant
    quant_act_k<<<B_DIM * S_DIM, 256>>>(x, p_xb, p_as);

    // 2b. out_w split concat (independent; needed by step 6)
    wsplit_k<<<(n + 255) / 256, 256>>>(ow, p_wcat);

    // 3. QKV projections: exact integer GEMM on bf16 tensor cores
    BJobs j1 = {};
    for (int z = 0; z < 6; z++) {
        int w = z >> 1, batch = z & 1;
        j1.A[z] = p_xb + (size_t)batch * S_DIM * E_DIM;
        j1.W[z] = p_wb + (size_t)w * n;
        if (w == 0)
            j1.C[z] = p_q + (size_t)batch * S_DIM * E_DIM;
        else if (w == 1)
            j1.C[z] = p_k + (size_t)batch * T_DIM * E_DIM;
        else
            j1.C[z] = p_v + (size_t)batch * T_DIM * E_DIM;
        j1.rs[z] = p_as + (size_t)batch * S_DIM;
        j1.ws[z] = p_scales + w;
    }
    j1.bias = nullptr;
    cudaFuncSetAttribute(bgemm_nt, cudaFuncAttributeMaxDynamicSharedMemorySize,
                         65536);
    bgemm_nt<<<dim3(16, 16, 6), 256, 65536>>>(j1, S_DIM, E_DIM, E_DIM);

    // 4. reasoning rk/rv (UNquantized, fp32), 128x64 tiles for parallelism
    GemmJobs j2 = {};
    for (int z = 0; z < 4; z++) {
        int w = z >> 1, batch = z & 1;
        j2.A[z] = rt + (size_t)batch * R_DIM * E_DIM;
        j2.W[z] = (w == 0) ? kw : vw;
        j2.C[z] = ((w == 0) ? p_k : p_v) + (size_t)batch * T_DIM * E_DIM +
                  (size_t)S_DIM * E_DIM;
    }
    sgemm_nt64<<<dim3(32, 1, 4), 256>>>(j2, R_DIM, E_DIM, E_DIM);

    // 5. tensor-core flash attention -> AO split concat
    cudaFuncSetAttribute(attn_tc, cudaFuncAttributeMaxDynamicSharedMemorySize,
                         ATT_SMEM);
    attn_tc<<<dim3(S_DIM / 128, H_DIM, B_DIM), 256, ATT_SMEM>>>(p_q, p_k, p_v,
                                                                p_acat);

    // 6. output projection: split bf16 GEMM over K'=6144 + bias
    BJobs j3 = {};
    j3.A[0] = p_acat;
    j3.W[0] = p_wcat;
    j3.C[0] = out;
    j3.rs[0] = nullptr;
    j3.ws[0] = nullptr;
    j3.bias = ob;
    bgemm_nt<<<dim3(16, 32, 1), 256, 65536>>>(j3, B_DIM * S_DIM, E_DIM, KCAT);
}

// round 5
// speedup vs baseline: 3.3223x; 1.7069x over previous
#include <cuda_runtime.h>
#include <cuda_bf16.h>
#include <math.h>
#include <stdint.h>

#define E_DIM 2048
#define B_DIM 2
#define S_DIM 2048
#define R_DIM 128
#define H_DIM 16
#define D_DIM 128
#define T_DIM (S_DIM + R_DIM)   /* 2176 */
#define KCAT (3 * E_DIM)        /* 6144 */
#define ROWW 4096               /* per-token split row: H*256 bf16 */

// ---------------- scratch -----------------------------------------------------
__device__ __nv_bfloat16 g_wb[3][E_DIM * E_DIM];        // ternary weights bf16
__device__ __nv_bfloat16 g_xb[B_DIM * S_DIM * E_DIM];   // int8-valued acts bf16
__device__ float g_as[B_DIM * S_DIM];                   // per-token 1/s
__device__ __nv_bfloat16 g_qs[(size_t)B_DIM * S_DIM * ROWW]; // Q split [b][s][h][hi|lo]
__device__ __nv_bfloat16 g_ks[(size_t)B_DIM * T_DIM * ROWW]; // K split
__device__ __nv_bfloat16 g_vs[(size_t)B_DIM * T_DIM * ROWW]; // V split
__device__ __nv_bfloat16 g_acat[(size_t)B_DIM * S_DIM * KCAT]; // [AOh|AOl|AOh]
__device__ __nv_bfloat16 g_wcat[(size_t)E_DIM * KCAT];         // [OWh|OWh|OWl]
__device__ float g_part[3 * 1024];
__device__ float g_scales[3];

// ---------------- prep kernels ------------------------------------------------
__global__ void absmean_partial(const float* __restrict__ w,
                                float* __restrict__ part, int n) {
    __shared__ float red[256];
    int chunk = n / gridDim.x;
    int base = blockIdx.x * chunk;
    float s = 0.f;
    for (int i = threadIdx.x; i < chunk; i += blockDim.x) s += fabsf(w[base + i]);
    red[threadIdx.x] = s;
    __syncthreads();
    for (int off = 128; off > 0; off >>= 1) {
        if (threadIdx.x < off) red[threadIdx.x] += red[threadIdx.x + off];
        __syncthreads();
    }
    if (threadIdx.x == 0) part[blockIdx.x] = red[0];
}

__global__ void scale_finalize(const float* __restrict__ part,
                               float* __restrict__ scales, int nblk, float inv_n) {
    __shared__ float red[256];
    const float* p = part + blockIdx.x * nblk;
    float s = 0.f;
    for (int i = threadIdx.x; i < nblk; i += blockDim.x) s += p[i];
    red[threadIdx.x] = s;
    __syncthreads();
    for (int off = 128; off > 0; off >>= 1) {
        if (threadIdx.x < off) red[threadIdx.x] += red[threadIdx.x + off];
        __syncthreads();
    }
    if (threadIdx.x == 0) scales[blockIdx.x] = fmaxf(red[0] * inv_n, 1e-5f);
}

__global__ void quant_weight_k(const float* __restrict__ w,
                               __nv_bfloat16* __restrict__ wb,
                               const float* __restrict__ scales, int sidx, int n) {
    float sc = scales[sidx];
    for (int i = blockIdx.x * blockDim.x + threadIdx.x; i < n;
         i += gridDim.x * blockDim.x) {
        float q = rintf(__fdiv_rn(w[i], sc));
        q = fminf(fmaxf(q, -1.f), 1.f);
        wb[i] = __float2bfloat16(q);
    }
}

__global__ void quant_act_k(const float* __restrict__ x,
                            __nv_bfloat16* __restrict__ xb,
                            float* __restrict__ as_) {
    __shared__ float red[256];
    int row = blockIdx.x;
    const float* xr = x + (size_t)row * E_DIM;
    __nv_bfloat16* qr = xb + (size_t)row * E_DIM;
    float m = 0.f;
    for (int i = threadIdx.x; i < E_DIM; i += blockDim.x) m = fmaxf(m, fabsf(xr[i]));
    red[threadIdx.x] = m;
    __syncthreads();
    for (int off = 128; off > 0; off >>= 1) {
        if (threadIdx.x < off)
            red[threadIdx.x] = fmaxf(red[threadIdx.x], red[threadIdx.x + off]);
        __syncthreads();
    }
    float mx = fmaxf(red[0], 1e-5f);
    float s = __fdiv_rn(127.f, mx);
    if (threadIdx.x == 0) as_[row] = __fdiv_rn(1.f, s);
    for (int i = threadIdx.x; i < E_DIM; i += blockDim.x) {
        float q = rintf(xr[i] * s);
        q = fminf(fmaxf(q, -128.f), 127.f);
        qr[i] = __float2bfloat16(q);
    }
}

__global__ void wsplit_k(const float* __restrict__ w,
                         __nv_bfloat16* __restrict__ wc) {
    int idx = blockIdx.x * blockDim.x + threadIdx.x;
    if (idx >= E_DIM * E_DIM) return;
    int r = idx / E_DIM, c = idx % E_DIM;
    float x = w[idx];
    __nv_bfloat16 h = __float2bfloat16(x);
    __nv_bfloat16 l = __float2bfloat16(x - __bfloat162float(h));
    size_t base = (size_t)r * KCAT + c;
    wc[base] = h;
    wc[base + E_DIM] = h;
    wc[base + 2 * E_DIM] = l;
}

// ---------------- bf16 tensor-core NT GEMM -----------------------------------
struct BJobs {
    const __nv_bfloat16* A[6];
    const __nv_bfloat16* W[6];
    float* C[6];            // split: cast to bf16*
    const float* rs[6];
    const float* ws[6];
    int split[6];
    const float* bias;
};

__device__ __forceinline__ uint32_t swz(uint32_t o) { return o ^ ((o >> 3) & 0x70); }

__global__ __launch_bounds__(256, 1) void bgemm_nt(BJobs jobs, int M, int N, int K) {
    extern __shared__ __align__(128) char sm_raw[];
    int z = blockIdx.z;
    const __nv_bfloat16* A = jobs.A[z];
    const __nv_bfloat16* W = jobs.W[z];
    const float* rs = jobs.rs[z];
    const float* ws = jobs.ws[z];

    uint32_t sbase = (uint32_t)__cvta_generic_to_shared(sm_raw);
    int tid = threadIdx.x, lane = tid & 31, warp = tid >> 5;
    int wm = warp >> 1, wn = warp & 1;
    int bm = blockIdx.y * 128, bn = blockIdx.x * 128;

    const __nv_bfloat16* Ag = A + (size_t)bm * K;
    const __nv_bfloat16* Wg = W + (size_t)bn * K;

    float acc[2][8][4];
#pragma unroll
    for (int mf = 0; mf < 2; mf++)
#pragma unroll
        for (int nf = 0; nf < 8; nf++)
#pragma unroll
            for (int c = 0; c < 4; c++) acc[mf][nf][c] = 0.f;

    float4 sa[4], sw[4];
#pragma unroll
    for (int i = 0; i < 4; i++) {
        int idx = i * 256 + tid;
        int row = idx >> 3, c = idx & 7;
        sa[i] = *(const float4*)(Ag + (size_t)row * K + c * 8);
        sw[i] = *(const float4*)(Wg + (size_t)row * K + c * 8);
    }
#pragma unroll
    for (int i = 0; i < 4; i++) {
        int idx = i * 256 + tid;
        int row = idx >> 3, c = idx & 7;
        uint32_t off = swz((uint32_t)(row * 128 + c * 16));
        *(float4*)(sm_raw + off) = sa[i];
        *(float4*)(sm_raw + 16384 + off) = sw[i];
    }
    __syncthreads();

    int KT = K >> 6;
    for (int kt = 0; kt < KT; kt++) {
        int cur = kt & 1;
        if (kt + 1 < KT) {
#pragma unroll
            for (int i = 0; i < 4; i++) {
                int idx = i * 256 + tid;
                int row = idx >> 3, c = idx & 7;
                sa[i] = *(const float4*)(Ag + (size_t)row * K + (kt + 1) * 64 + c * 8);
                sw[i] = *(const float4*)(Wg + (size_t)row * K + (kt + 1) * 64 + c * 8);
            }
        }
        uint32_t abase = sbase + cur * 32768;
        uint32_t wbase = abase + 16384;
#pragma unroll
        for (int ks = 0; ks < 4; ks++) {
            uint32_t a[2][4];
#pragma unroll
            for (int mf = 0; mf < 2; mf++) {
                int r = wm * 32 + mf * 16 + ((lane >> 3) & 1) * 8 + (lane & 7);
                uint32_t off = swz((uint32_t)(r * 128 + ks * 32 + ((lane >> 4) & 1) * 16));
                asm volatile(
                    "ldmatrix.sync.aligned.m8n8.x4.shared.b16 {%0,%1,%2,%3}, [%4];"
                    : "=r"(a[mf][0]), "=r"(a[mf][1]), "=r"(a[mf][2]), "=r"(a[mf][3])
                    : "r"(abase + off));
            }
            uint32_t b0[8], b1[8];
#pragma unroll
            for (int q = 0; q < 4; q++) {
                int r = wn * 64 + q * 16 + ((lane >> 3) & 1) * 8 + (lane & 7);
                uint32_t off = swz((uint32_t)(r * 128 + ks * 32 + ((lane >> 4) & 1) * 16));
                uint32_t r0, r1, r2, r3;
                asm volatile(
                    "ldmatrix.sync.aligned.m8n8.x4.shared.b16 {%0,%1,%2,%3}, [%4];"
                    : "=r"(r0), "=r"(r1), "=r"(r2), "=r"(r3)
                    : "r"(wbase + off));
                b0[2 * q] = r0; b0[2 * q + 1] = r1;
                b1[2 * q] = r2; b1[2 * q + 1] = r3;
            }
#pragma unroll
            for (int mf = 0; mf < 2; mf++)
#pragma unroll
                for (int nf = 0; nf < 8; nf++)
                    asm volatile(
                        "mma.sync.aligned.m16n8k16.row.col.f32.bf16.bf16.f32 "
                        "{%0,%1,%2,%3},{%4,%5,%6,%7},{%8,%9},{%0,%1,%2,%3};"
                        : "+f"(acc[mf][nf][0]), "+f"(acc[mf][nf][1]),
                          "+f"(acc[mf][nf][2]), "+f"(acc[mf][nf][3])
                        : "r"(a[mf][0]), "r"(a[mf][1]), "r"(a[mf][2]), "r"(a[mf][3]),
                          "r"(b0[nf]), "r"(b1[nf]));
        }
        if (kt + 1 < KT) {
            int nxt = cur ^ 1;
#pragma unroll
            for (int i = 0; i < 4; i++) {
                int idx = i * 256 + tid;
                int row = idx >> 3, c = idx & 7;
                uint32_t off = swz((uint32_t)(row * 128 + c * 16));
                *(float4*)(sm_raw + nxt * 32768 + off) = sa[i];
                *(float4*)(sm_raw + nxt * 32768 + 16384 + off) = sw[i];
            }
        }
        __syncthreads();
    }

    int g = lane >> 2, t = lane & 3;
    float wsv = ws ? *ws : 1.f;
    if (jobs.split[z]) {
        // write hi/lo bf16 pairs into [token][h][hi128|lo128] layout
        __nv_bfloat16* Ob = (__nv_bfloat16*)jobs.C[z];
#pragma unroll
        for (int mf = 0; mf < 2; mf++) {
            int row0 = bm + wm * 32 + mf * 16 + g;
            float r0s = (rs ? rs[row0] : 1.f) * wsv;
            float r1s = (rs ? rs[row0 + 8] : 1.f) * wsv;
#pragma unroll
            for (int nf = 0; nf < 8; nf++) {
                int col = bn + wn * 64 + nf * 8 + 2 * t;
                int hh = col >> 7, d = col & 127;
                size_t i0 = (size_t)row0 * ROWW + hh * 256 + d;
                size_t i8 = (size_t)(row0 + 8) * ROWW + hh * 256 + d;
                float v0 = acc[mf][nf][0] * r0s, v1 = acc[mf][nf][1] * r0s;
                float v2 = acc[mf][nf][2] * r1s, v3 = acc[mf][nf][3] * r1s;
                __nv_bfloat162 h0 = __floats2bfloat162_rn(v0, v1);
                __nv_bfloat162 l0 = __floats2bfloat162_rn(
                    v0 - __bfloat162float(h0.x), v1 - __bfloat162float(h0.y));
                __nv_bfloat162 h8 = __floats2bfloat162_rn(v2, v3);
                __nv_bfloat162 l8 = __floats2bfloat162_rn(
                    v2 - __bfloat162float(h8.x), v3 - __bfloat162float(h8.y));
                *(__nv_bfloat162*)&Ob[i0] = h0;
                *(__nv_bfloat162*)&Ob[i0 + 128] = l0;
                *(__nv_bfloat162*)&Ob[i8] = h8;
                *(__nv_bfloat162*)&Ob[i8 + 128] = l8;
            }
        }
    } else {
        float* C = jobs.C[z];
        const float* bias = jobs.bias;
#pragma unroll
        for (int mf = 0; mf < 2; mf++) {
            int row0 = bm + wm * 32 + mf * 16 + g;
            float r0s = (rs ? rs[row0] : 1.f) * wsv;
            float r1s = (rs ? rs[row0 + 8] : 1.f) * wsv;
#pragma unroll
            for (int nf = 0; nf < 8; nf++) {
                int col = bn + wn * 64 + nf * 8 + 2 * t;
                float b0v = bias ? bias[col] : 0.f;
                float b1v = bias ? bias[col + 1] : 0.f;
                float2 v0 = make_float2(acc[mf][nf][0] * r0s + b0v,
                                        acc[mf][nf][1] * r0s + b1v);
                float2 v1 = make_float2(acc[mf][nf][2] * r1s + b0v,
                                        acc[mf][nf][3] * r1s + b1v);
                *(float2*)&C[(size_t)row0 * N + col] = v0;
                *(float2*)&C[(size_t)(row0 + 8) * N + col] = v1;
            }
        }
    }
}

// ---------------- fp32 NT SGEMM 128x64 (rk/rv) -> split bf16 out -------------
struct GemmJobs {
    const float* A[4];
    const float* W[4];
    __nv_bfloat16* C[4];   // split layout base (already offset to row S)
};

__global__ __launch_bounds__(256) void sgemm_nt64(GemmJobs jobs, int M, int N, int K) {
    __shared__ __align__(16) float As[128][20];
    __shared__ __align__(16) float Ws[64][20];
    const float* A = jobs.A[blockIdx.z];
    const float* W = jobs.W[blockIdx.z];
    __nv_bfloat16* C = jobs.C[blockIdx.z];
    int tid = threadIdx.x;
    int tx = tid & 15, ty = tid >> 4;
    int bn = blockIdx.x * 64;

    float acc[8][4];
#pragma unroll
    for (int i = 0; i < 8; i++)
#pragma unroll
        for (int j = 0; j < 4; j++) acc[i][j] = 0.f;

    for (int kt = 0; kt < K; kt += 16) {
#pragma unroll
        for (int it = 0; it < 2; it++) {
            int idx = tid + it * 256;
            int row = idx >> 2, k4 = (idx & 3) * 4;
            *(float4*)&As[row][k4] =
                *(const float4*)&A[(size_t)row * K + kt + k4];
        }
        {
            int row = tid >> 2, k4 = (tid & 3) * 4;
            *(float4*)&Ws[row][k4] =
                *(const float4*)&W[(size_t)(bn + row) * K + kt + k4];
        }
        __syncthreads();
#pragma unroll
        for (int k4 = 0; k4 < 16; k4 += 4) {
            float4 a[8], b[4];
#pragma unroll
            for (int i = 0; i < 8; i++) a[i] = *(float4*)&As[ty + 16 * i][k4];
#pragma unroll
            for (int j = 0; j < 4; j++) b[j] = *(float4*)&Ws[tx + 16 * j][k4];
#pragma unroll
            for (int i = 0; i < 8; i++)
#pragma unroll
                for (int j = 0; j < 4; j++)
                    acc[i][j] += a[i].x * b[j].x + a[i].y * b[j].y +
                                 a[i].z * b[j].z + a[i].w * b[j].w;
        }
        __syncthreads();
    }
#pragma unroll
    for (int i = 0; i < 8; i++) {
        int r = ty + 16 * i;
#pragma unroll
        for (int j = 0; j < 4; j++) {
            int n = bn + tx + 16 * j;
            int hh = n >> 7, d = n & 127;
            float v = acc[i][j];
            __nv_bfloat16 h = __float2bfloat16(v);
            __nv_bfloat16 l = __float2bfloat16(v - __bfloat162float(h));
            C[(size_t)r * ROWW + hh * 256 + d] = h;
            C[(size_t)r * ROWW + hh * 256 + d + 128] = l;
        }
    }
}

// ---------------- tensor-core flash attention (pre-split, cp.async) ----------
// BQ=128, BK=64, 256 threads (8 warps). K & V double buffered.
#define ATT_Q_OFF 0            /* [128][512B] */
#define ATT_K_OFF 65536        /* 2 x [64][512B] */
#define ATT_V_OFF 131072       /* 2 x [128][256B] (Vh rows 0-63, Vl 64-127) */
#define ATT_P_OFF 196608       /* [128][256B]: cols 0-63 Ph, 64-127 Pl */
#define ATT_SMEM 229376

__device__ __forceinline__ uint32_t sw512o(int r, int c) {
    return (uint32_t)(r * 512 + ((((c >> 3) ^ (r & 7))) << 4) + ((c & 7) << 1));
}
__device__ __forceinline__ uint32_t sw256o(int r, int c) {
    return (uint32_t)(r * 256 + ((((c >> 3) ^ (r & 7))) << 4) + ((c & 7) << 1));
}
__device__ __forceinline__ void ldsm4(uint32_t addr, uint32_t& r0, uint32_t& r1,
                                      uint32_t& r2, uint32_t& r3) {
    asm volatile("ldmatrix.sync.aligned.m8n8.x4.shared.b16 {%0,%1,%2,%3}, [%4];"
                 : "=r"(r0), "=r"(r1), "=r"(r2), "=r"(r3) : "r"(addr));
}
__device__ __forceinline__ void ldsm4t(uint32_t addr, uint32_t& r0, uint32_t& r1,
                                       uint32_t& r2, uint32_t& r3) {
    asm volatile("ldmatrix.sync.aligned.m8n8.x4.trans.shared.b16 {%0,%1,%2,%3}, [%4];"
                 : "=r"(r0), "=r"(r1), "=r"(r2), "=r"(r3) : "r"(addr));
}
__device__ __forceinline__ void cpa16(uint32_t dst, const void* src) {
    asm volatile("cp.async.cg.shared.global [%0], [%1], 16;" :: "r"(dst), "l"(src));
}
__device__ __forceinline__ void cp_commit() {
    asm volatile("cp.async.commit_group;" ::: "memory");
}

__global__ __launch_bounds__(256, 1) void attn_tc(const __nv_bfloat16* __restrict__ Qs,
                                                  const __nv_bfloat16* __restrict__ Ks,
                                                  const __nv_bfloat16* __restrict__ Vs,
                                                  __nv_bfloat16* __restrict__ AOcat) {
    extern __shared__ __align__(128) char smc[];
    uint32_t sb = (uint32_t)__cvta_generic_to_shared(smc);

    int tid = threadIdx.x, lane = tid & 31, w = tid >> 5;
    int g = lane >> 2, t = lane & 3;
    int q0 = blockIdx.x * 128;
    int h = blockIdx.y, b = blockIdx.z;

    const __nv_bfloat16* Qg = Qs + ((size_t)(b * S_DIM + q0) * H_DIM + h) * 256;
    const __nv_bfloat16* Kg = Ks + ((size_t)(b * T_DIM) * H_DIM + h) * 256;
    const __nv_bfloat16* Vg = Vs + ((size_t)(b * T_DIM) * H_DIM + h) * 256;

    const int NT = T_DIM / 64;  // 34

    // prologue: Q + K0 | V0 | K1 | V1 (4 commit groups)
#pragma unroll
    for (int it = 0; it < 16; it++) {
        int idx = it * 256 + tid;
        int r = idx >> 5, c = (idx & 31) * 8;
        cpa16(sb + ATT_Q_OFF + sw512o(r, c), Qg + (size_t)r * ROWW + c);
    }
#pragma unroll
    for (int it = 0; it < 8; it++) {
        int idx = it * 256 + tid;
        int r = idx >> 5, c = (idx & 31) * 8;
        cpa16(sb + ATT_K_OFF + sw512o(r, c), Kg + (size_t)r * ROWW + c);
    }
    cp_commit();
#pragma unroll
    for (int it = 0; it < 8; it++) {
        int idx = it * 256 + tid;
        int r = idx >> 5, ch = idx & 31;
        uint32_t dst = (ch < 16) ? sb + ATT_V_OFF + sw256o(r, ch * 8)
                                 : sb + ATT_V_OFF + sw256o(64 + r, (ch - 16) * 8);
        cpa16(dst, Vg + (size_t)r * ROWW + ch * 8);
    }
    cp_commit();
#pragma unroll
    for (int it = 0; it < 8; it++) {
        int idx = it * 256 + tid;
        int r = idx >> 5, c = (idx & 31) * 8;
        cpa16(sb + ATT_K_OFF + 32768 + sw512o(r, c),
              Kg + (size_t)(64 + r) * ROWW + c);
    }
    cp_commit();
#pragma unroll
    for (int it = 0; it < 8; it++) {
        int idx = it * 256 + tid;
        int r = idx >> 5, ch = idx & 31;
        uint32_t dst = (ch < 16) ? sb + ATT_V_OFF + 32768 + sw256o(r, ch * 8)
                                 : sb + ATT_V_OFF + 32768 + sw256o(64 + r, (ch - 16) * 8);
        cpa16(dst, Vg + (size_t)(64 + r) * ROWW + ch * 8);
    }
    cp_commit();

    float o[16][4];
#pragma unroll
    for (int nf = 0; nf < 16; nf++)
#pragma unroll
        for (int c = 0; c < 4; c++) o[nf][c] = 0.f;
    float m0 = -1e30f, m8 = -1e30f, l0 = 0.f, l8 = 0.f;

    const float scl = 0.08838834764831845f;  // 1/sqrt(128)
    int rg = w * 16 + g;

    for (int i = 0; i < NT; i++) {
        asm volatile("cp.async.wait_group 2;" ::: "memory");
        __syncthreads();

        uint32_t kbuf = sb + ATT_K_OFF + (i & 1) * 32768;
        uint32_t vbuf = sb + ATT_V_OFF + (i & 1) * 32768;

        // ---- QK: 3-term split, 24 k16 steps ----
        float accs[8][4];
#pragma unroll
        for (int nf = 0; nf < 8; nf++)
#pragma unroll
            for (int c = 0; c < 4; c++) accs[nf][c] = 0.f;

#pragma unroll
        for (int s = 0; s < 24; s++) {
            int aoff = (s < 8) ? s * 16 : (s < 16) ? 128 + (s - 8) * 16 : (s - 16) * 16;
            int boff = (s < 8) ? s * 16 : (s < 16) ? (s - 8) * 16 : 128 + (s - 16) * 16;
            uint32_t a0, a1, a2, a3;
            {
                int ar = w * 16 + ((lane >> 3) & 1) * 8 + (lane & 7);
                int ac = aoff + ((lane >> 4) & 1) * 8;
                ldsm4(sb + ATT_Q_OFF + sw512o(ar, ac), a0, a1, a2, a3);
            }
            uint32_t b0[8], b1[8];
#pragma unroll
            for (int nb = 0; nb < 4; nb++) {
                int br = nb * 16 + ((lane >> 3) & 1) * 8 + (lane & 7);
                int bc = boff + ((lane >> 4) & 1) * 8;
                uint32_t r0, r1, r2, r3;
                ldsm4(kbuf + sw512o(br, bc), r0, r1, r2, r3);
                b0[2 * nb] = r0; b0[2 * nb + 1] = r1;
                b1[2 * nb] = r2; b1[2 * nb + 1] = r3;
            }
#pragma unroll
            for (int nf = 0; nf < 8; nf++)
                asm volatile(
                    "mma.sync.aligned.m16n8k16.row.col.f32.bf16.bf16.f32 "
                    "{%0,%1,%2,%3},{%4,%5,%6,%7},{%8,%9},{%0,%1,%2,%3};"
                    : "+f"(accs[nf][0]), "+f"(accs[nf][1]),
                      "+f"(accs[nf][2]), "+f"(accs[nf][3])
                    : "r"(a0), "r"(a1), "r"(a2), "r"(a3),
                      "r"(b0[nf]), "r"(b1[nf]));
        }

        // ---- register-space online softmax ----
        float mx0 = -1e30f, mx8 = -1e30f;
#pragma unroll
        for (int nf = 0; nf < 8; nf++) {
            accs[nf][0] *= scl; accs[nf][1] *= scl;
            accs[nf][2] *= scl; accs[nf][3] *= scl;
            mx0 = fmaxf(mx0, fmaxf(accs[nf][0], accs[nf][1]));
            mx8 = fmaxf(mx8, fmaxf(accs[nf][2], accs[nf][3]));
        }
        mx0 = fmaxf(mx0, __shfl_xor_sync(0xffffffffu, mx0, 1));
        mx0 = fmaxf(mx0, __shfl_xor_sync(0xffffffffu, mx0, 2));
        mx8 = fmaxf(mx8, __shfl_xor_sync(0xffffffffu, mx8, 1));
        mx8 = fmaxf(mx8, __shfl_xor_sync(0xffffffffu, mx8, 2));
        float mn0 = fmaxf(m0, mx0), mn8 = fmaxf(m8, mx8);
        float al0 = __expf(m0 - mn0), al8 = __expf(m8 - mn8);
        m0 = mn0; m8 = mn8;
        float sum0 = 0.f, sum8 = 0.f;
#pragma unroll
        for (int nf = 0; nf < 8; nf++) {
            int c = nf * 8 + 2 * t;
            float p0 = __expf(accs[nf][0] - mn0);
            float p1 = __expf(accs[nf][1] - mn0);
            sum0 += p0 + p1;
            __nv_bfloat162 ph = __floats2bfloat162_rn(p0, p1);
            __nv_bfloat162 pl = __floats2bfloat162_rn(
                p0 - __bfloat162float(ph.x), p1 - __bfloat162float(ph.y));
            *(__nv_bfloat162*)(smc + ATT_P_OFF + sw256o(rg, c)) = ph;
            *(__nv_bfloat162*)(smc + ATT_P_OFF + sw256o(rg, 64 + c)) = pl;
            float p2 = __expf(accs[nf][2] - mn8);
            float p3 = __expf(accs[nf][3] - mn8);
            sum8 += p2 + p3;
            __nv_bfloat162 qh = __floats2bfloat162_rn(p2, p3);
            __nv_bfloat162 ql = __floats2bfloat162_rn(
                p2 - __bfloat162float(qh.x), p3 - __bfloat162float(qh.y));
            *(__nv_bfloat162*)(smc + ATT_P_OFF + sw256o(rg + 8, c)) = qh;
            *(__nv_bfloat162*)(smc + ATT_P_OFF + sw256o(rg + 8, 64 + c)) = ql;
        }
        sum0 += __shfl_xor_sync(0xffffffffu, sum0, 1);
        sum0 += __shfl_xor_sync(0xffffffffu, sum0, 2);
        sum8 += __shfl_xor_sync(0xffffffffu, sum8, 1);
        sum8 += __shfl_xor_sync(0xffffffffu, sum8, 2);
        l0 = l0 * al0 + sum0;
        l8 = l8 * al8 + sum8;
#pragma unroll
        for (int nf = 0; nf < 16; nf++) {
            o[nf][0] *= al0; o[nf][1] *= al0;
            o[nf][2] *= al8; o[nf][3] *= al8;
        }
        __syncwarp();

        // ---- PV: 3-term split, 12 k16 steps ----
#pragma unroll
        for (int s = 0; s < 12; s++) {
            int pcol = (s < 4) ? s * 16 : (s < 8) ? 64 + (s - 4) * 16 : (s - 8) * 16;
            int vrow = (s < 4) ? s * 16 : (s < 8) ? (s - 4) * 16 : 64 + (s - 8) * 16;
            uint32_t a0, a1, a2, a3;
            {
                int ar = w * 16 + ((lane >> 3) & 1) * 8 + (lane & 7);
                int ac = pcol + ((lane >> 4) & 1) * 8;
                ldsm4(sb + ATT_P_OFF + sw256o(ar, ac), a0, a1, a2, a3);
            }
#pragma unroll
            for (int ng = 0; ng < 8; ng++) {
                int vr = vrow + ((lane >> 3) & 1) * 8 + (lane & 7);
                int vc = ng * 16 + ((lane >> 4) & 1) * 8;
                uint32_t r0, r1, r2, r3;
                ldsm4t(vbuf + sw256o(vr, vc), r0, r1, r2, r3);
                asm volatile(
                    "mma.sync.aligned.m16n8k16.row.col.f32.bf16.bf16.f32 "
                    "{%0,%1,%2,%3},{%4,%5,%6,%7},{%8,%9},{%0,%1,%2,%3};"
                    : "+f"(o[2 * ng][0]), "+f"(o[2 * ng][1]),
                      "+f"(o[2 * ng][2]), "+f"(o[2 * ng][3])
                    : "r"(a0), "r"(a1), "r"(a2), "r"(a3), "r"(r0), "r"(r1));
                asm volatile(
                    "mma.sync.aligned.m16n8k16.row.col.f32.bf16.bf16.f32 "
                    "{%0,%1,%2,%3},{%4,%5,%6,%7},{%8,%9},{%0,%1,%2,%3};"
                    : "+f"(o[2 * ng + 1][0]), "+f"(o[2 * ng + 1][1]),
                      "+f"(o[2 * ng + 1][2]), "+f"(o[2 * ng + 1][3])
                    : "r"(a0), "r"(a1), "r"(a2), "r"(a3), "r"(r2), "r"(r3));
            }
        }
        __syncthreads();

        // ---- prefetch tile i+2 into buffer (i&1) ----
        if (i + 2 < NT) {
            int tK = (i + 2) * 64;
            uint32_t kb2 = sb + ATT_K_OFF + (i & 1) * 32768;
#pragma unroll
            for (int it = 0; it < 8; it++) {
                int idx = it * 256 + tid;
                int r = idx >> 5, c = (idx & 31) * 8;
                cpa16(kb2 + sw512o(r, c), Kg + (size_t)(tK + r) * ROWW + c);
            }
        }
        cp_commit();
        if (i + 2 < NT) {
            int tV = (i + 2) * 64;
            uint32_t vb2 = sb + ATT_V_OFF + (i & 1) * 32768;
#pragma unroll
            for (int it = 0; it < 8; it++) {
                int idx = it * 256 + tid;
                int r = idx >> 5, ch = idx & 31;
                uint32_t dst = (ch < 16) ? vb2 + sw256o(r, ch * 8)
                                         : vb2 + sw256o(64 + r, (ch - 16) * 8);
                cpa16(dst, Vg + (size_t)(tV + r) * ROWW + ch * 8);
            }
        }
        cp_commit();
    }

    // epilogue: normalize and write hi/lo concat rows of AOcat
    {
        float li0 = __fdiv_rn(1.f, l0);
        float li8 = __fdiv_rn(1.f, l8);
        size_t grow0 = (size_t)(b * S_DIM + q0 + rg) * KCAT + h * D_DIM;
        size_t grow8 = grow0 + (size_t)8 * KCAT;
#pragma unroll
        for (int nf = 0; nf < 16; nf++) {
            int c = nf * 8 + 2 * t;
            float f0 = o[nf][0] * li0, f1 = o[nf][1] * li0;
            float f2 = o[nf][2] * li8, f3 = o[nf][3] * li8;
            __nv_bfloat162 h0 = __floats2bfloat162_rn(f0, f1);
            __nv_bfloat162 ll0 = __floats2bfloat162_rn(f0 - __bfloat162float(h0.x),
                                                       f1 - __bfloat162float(h0.y));
            __nv_bfloat162 h8 = __floats2bfloat162_rn(f2, f3);
            __nv_bfloat162 ll8 = __floats2bfloat162_rn(f2 - __bfloat162float(h8.x),
                                                       f3 - __bfloat162float(h8.y));
            *(__nv_bfloat162*)&AOcat[grow0 + c] = h0;
            *(__nv_bfloat162*)&AOcat[grow0 + E_DIM + c] = ll0;
            *(__nv_bfloat162*)&AOcat[grow0 + 2 * E_DIM + c] = h0;
            *(__nv_bfloat162*)&AOcat[grow8 + c] = h8;
            *(__nv_bfloat162*)&AOcat[grow8 + E_DIM + c] = ll8;
            *(__nv_bfloat162*)&AOcat[grow8 + 2 * E_DIM + c] = h8;
        }
    }
}

// ---------------- launcher ----------------------------------------------------
extern "C" void kernel_launch(void* const* d_in, const int* in_sizes, int n_in,
                              void* d_out, int out_size) {
    const float* x  = (const float*)d_in[0];
    const float* rt = (const float*)d_in[1];
    const float* qw = (const float*)d_in[2];
    const float* kw = (const float*)d_in[3];
    const float* vw = (const float*)d_in[4];
    const float* ow = (const float*)d_in[5];
    const float* ob = (const float*)d_in[6];
    float* out = (float*)d_out;

    __nv_bfloat16 *p_wb, *p_xb, *p_qs, *p_ks, *p_vs, *p_acat, *p_wcat;
    float *p_as, *p_part, *p_scales;
    cudaGetSymbolAddress((void**)&p_wb, g_wb);
    cudaGetSymbolAddress((void**)&p_xb, g_xb);
    cudaGetSymbolAddress((void**)&p_as, g_as);
    cudaGetSymbolAddress((void**)&p_qs, g_qs);
    cudaGetSymbolAddress((void**)&p_ks, g_ks);
    cudaGetSymbolAddress((void**)&p_vs, g_vs);
    cudaGetSymbolAddress((void**)&p_acat, g_acat);
    cudaGetSymbolAddress((void**)&p_wcat, g_wcat);
    cudaGetSymbolAddress((void**)&p_part, g_part);
    cudaGetSymbolAddress((void**)&p_scales, g_scales);

    const int n = E_DIM * E_DIM;

    // 1. ternary weight scales + bf16 ternary weights
    absmean_partial<<<1024, 256>>>(qw, p_part + 0 * 1024, n);
    absmean_partial<<<1024, 256>>>(kw, p_part + 1 * 1024, n);
    absmean_partial<<<1024, 256>>>(vw, p_part + 2 * 1024, n);
    scale_finalize<<<3, 256>>>(p_part, p_scales, 1024, 1.f / (float)n);
    quant_weight_k<<<2048, 256>>>(qw, p_wb + 0 * (size_t)n, p_scales, 0, n);
    quant_weight_k<<<2048, 256>>>(kw, p_wb + 1 * (size_t)n, p_scales, 1, n);
    quant_weight_k<<<2048, 256>>>(vw, p_wb + 2 * (size_t)n, p_scales, 2, n);

    // 2. per-token activation quant + out_w split concat
    quant_act_k<<<B_DIM * S_DIM, 256>>>(x, p_xb, p_as);
    wsplit_k<<<(n + 255) / 256, 256>>>(ow, p_wcat);

    // 3. QKV projections -> split bf16 [token][h][hi|lo]
    BJobs j1 = {};
    for (int z = 0; z < 6; z++) {
        int w = z >> 1, batch = z & 1;
        j1.A[z] = p_xb + (size_t)batch * S_DIM * E_DIM;
        j1.W[z] = p_wb + (size_t)w * n;
        if (w == 0)
            j1.C[z] = (float*)(p_qs + (size_t)batch * S_DIM * ROWW);
        else if (w == 1)
            j1.C[z] = (float*)(p_ks + (size_t)batch * T_DIM * ROWW);
        else
            j1.C[z] = (float*)(p_vs + (size_t)batch * T_DIM * ROWW);
        j1.rs[z] = p_as + (size_t)batch * S_DIM;
        j1.ws[z] = p_scales + w;
        j1.split[z] = 1;
    }
    j1.bias = nullptr;
    cudaFuncSetAttribute(bgemm_nt, cudaFuncAttributeMaxDynamicSharedMemorySize,
                         65536);
    bgemm_nt<<<dim3(16, 16, 6), 256, 65536>>>(j1, S_DIM, E_DIM, E_DIM);

    // 4. reasoning rk/rv -> split bf16 rows S..T
    GemmJobs j2 = {};
    for (int z = 0; z < 4; z++) {
        int w = z >> 1, batch = z & 1;
        j2.A[z] = rt + (size_t)batch * R_DIM * E_DIM;
        j2.W[z] = (w == 0) ? kw : vw;
        j2.C[z] = ((w == 0) ? p_ks : p_vs) +
                  ((size_t)batch * T_DIM + S_DIM) * ROWW;
    }
    sgemm_nt64<<<dim3(32, 1, 4), 256>>>(j2, R_DIM, E_DIM, E_DIM);

    // 5. pipelined tensor-core flash attention -> AO split concat
    cudaFuncSetAttribute(attn_tc, cudaFuncAttributeMaxDynamicSharedMemorySize,
                         ATT_SMEM);
    attn_tc<<<dim3(S_DIM / 128, H_DIM, B_DIM), 256, ATT_SMEM>>>(p_qs, p_ks, p_vs,
                                                                p_acat);

    // 6. output projection: split bf16 GEMM over K'=6144 + bias
    BJobs j3 = {};
    j3.A[0] = p_acat;
    j3.W[0] = p_wcat;
    j3.C[0] = out;
    j3.rs[0] = nullptr;
    j3.ws[0] = nullptr;
    j3.split[0] = 0;
    j3.bias = ob;
    bgemm_nt<<<dim3(16, 32, 1), 256, 65536>>>(j3, B_DIM * S_DIM, E_DIM, KCAT);
}